// round 1
// baseline (speedup 1.0000x reference)
#include <cuda_runtime.h>
#include <math.h>

#define Bn 256
#define Sn 141
#define Vn 1000
#define En 256
#define Hn 512
#define G4 2048   // 4*H

// Scratch (device globals: allocation-free rule)
__device__ float d_embgate[Vn * G4];              // 8 MB: emb[v] @ W_ih[:, :E]^T
__device__ float d_encgate[Bn * G4];              // 2 MB: enc[b] @ W_ih[:, E:2E]^T + biases
__device__ float d_hs[(size_t)Sn * Bn * Hn];      // 74 MB: h per step, [t][b][k]
__device__ float d_c[Bn * Hn];                    // cell state (in-place per step)

#define MMA_STEP() do {                                                          \
    _Pragma("unroll")                                                            \
    for (int kk = 0; kk < 16; ++kk) {                                            \
      float4 a = *(const float4*)&As[kk][ty * 4];                                \
      float4 b = *(const float4*)&Bs[kk][tx * 4];                                \
      acc[0][0] += a.x*b.x; acc[0][1] += a.x*b.y; acc[0][2] += a.x*b.z; acc[0][3] += a.x*b.w; \
      acc[1][0] += a.y*b.x; acc[1][1] += a.y*b.y; acc[1][2] += a.y*b.z; acc[1][3] += a.y*b.w; \
      acc[2][0] += a.z*b.x; acc[2][1] += a.z*b.y; acc[2][2] += a.z*b.z; acc[2][3] += a.z*b.w; \
      acc[3][0] += a.w*b.x; acc[3][1] += a.w*b.y; acc[3][2] += a.w*b.z; acc[3][3] += a.w*b.w; \
    } } while (0)

// ---------------------------------------------------------------------------
// encgate[b][j] = sum_e enc[b][e] * W_ih[j][E+e] + b_ih[j] + b_hh[j]
// M=256, N=2048, K=256. grid(4,32), 256 thr, 64x64 tiles. No guards needed.
// ---------------------------------------------------------------------------
__global__ __launch_bounds__(256) void encgate_kernel(
    const float* __restrict__ enc, const float* __restrict__ Wih,
    const float* __restrict__ bih, const float* __restrict__ bhh) {
  __shared__ float As[16][64];
  __shared__ float Bs[16][64];
  int tid = threadIdx.x;
  int m0 = blockIdx.x * 64, n0 = blockIdx.y * 64;
  int tx = tid & 15, ty = tid >> 4;
  int lr = tid >> 2, lq = tid & 3;
  float acc[4][4] = {};
  for (int kc = 0; kc < En; kc += 16) {
    float4 av = *(const float4*)(enc + (size_t)(m0 + lr) * En + kc + lq * 4);
    float4 bv = *(const float4*)(Wih + (size_t)(n0 + lr) * (2 * En) + En + kc + lq * 4);
    __syncthreads();
    As[lq*4+0][lr] = av.x; As[lq*4+1][lr] = av.y; As[lq*4+2][lr] = av.z; As[lq*4+3][lr] = av.w;
    Bs[lq*4+0][lr] = bv.x; Bs[lq*4+1][lr] = bv.y; Bs[lq*4+2][lr] = bv.z; Bs[lq*4+3][lr] = bv.w;
    __syncthreads();
    MMA_STEP();
  }
#pragma unroll
  for (int ii = 0; ii < 4; ++ii) {
    int m = m0 + ty * 4 + ii;
#pragma unroll
    for (int jj = 0; jj < 4; ++jj) {
      int n = n0 + tx * 4 + jj;
      d_encgate[(size_t)m * G4 + n] = acc[ii][jj] + bih[n] + bhh[n];
    }
  }
}

// ---------------------------------------------------------------------------
// embgate[v][j] = sum_e emb[v][e] * W_ih[j][e].  M=1000 (guarded), N=2048, K=256.
// grid(16,32)
// ---------------------------------------------------------------------------
__global__ __launch_bounds__(256) void embgate_kernel(
    const float* __restrict__ emb, const float* __restrict__ Wih) {
  __shared__ float As[16][64];
  __shared__ float Bs[16][64];
  int tid = threadIdx.x;
  int m0 = blockIdx.x * 64, n0 = blockIdx.y * 64;
  int tx = tid & 15, ty = tid >> 4;
  int lr = tid >> 2, lq = tid & 3;
  float acc[4][4] = {};
  for (int kc = 0; kc < En; kc += 16) {
    float4 av = make_float4(0.f, 0.f, 0.f, 0.f);
    if (m0 + lr < Vn)
      av = *(const float4*)(emb + (size_t)(m0 + lr) * En + kc + lq * 4);
    float4 bv = *(const float4*)(Wih + (size_t)(n0 + lr) * (2 * En) + kc + lq * 4);
    __syncthreads();
    As[lq*4+0][lr] = av.x; As[lq*4+1][lr] = av.y; As[lq*4+2][lr] = av.z; As[lq*4+3][lr] = av.w;
    Bs[lq*4+0][lr] = bv.x; Bs[lq*4+1][lr] = bv.y; Bs[lq*4+2][lr] = bv.z; Bs[lq*4+3][lr] = bv.w;
    __syncthreads();
    MMA_STEP();
  }
#pragma unroll
  for (int ii = 0; ii < 4; ++ii) {
    int m = m0 + ty * 4 + ii;
    if (m >= Vn) continue;
#pragma unroll
    for (int jj = 0; jj < 4; ++jj) {
      int n = n0 + tx * 4 + jj;
      d_embgate[(size_t)m * G4 + n] = acc[ii][jj];
    }
  }
}

// ---------------------------------------------------------------------------
// One LSTM step, fully fused: gates = embgate[tok] + encgate + h_{t-1} @ W_hh^T,
// then LSTM elementwise -> h_t (to d_hs[t]), c (in-place).
// Block covers b in [b0,b0+64), k in [k0,k0+16) but ALL 4 gates:
// column c in [0,64): j = (c>>4)*512 + k0 + (c&15).
// grid(4,32), 256 threads.
// ---------------------------------------------------------------------------
__global__ __launch_bounds__(256) void step_kernel(
    const float* __restrict__ Whh, const int* __restrict__ tgt, int t) {
  __shared__ float As[16][64];
  __shared__ float Bs[16][64];
  __shared__ float Gs[4][64][16];
  __shared__ int toks[64];

  int tid = threadIdx.x;
  int b0 = blockIdx.x * 64;
  int k0 = blockIdx.y * 16;
  int tx = tid & 15, ty = tid >> 4;

  if (tid < 64) toks[tid] = tgt[(size_t)(b0 + tid) * Sn + t];

  float acc[4][4] = {};
  if (t > 0) {
    const float* hprev = d_hs + (size_t)(t - 1) * Bn * Hn;
    int lr = tid >> 2, lq = tid & 3;
    int jrow = (lr >> 4) * Hn + k0 + (lr & 15);   // W_hh row for column c=lr
    for (int kc = 0; kc < Hn; kc += 16) {
      float4 av = *(const float4*)(hprev + (size_t)(b0 + lr) * Hn + kc + lq * 4);
      float4 bv = *(const float4*)(Whh + (size_t)jrow * Hn + kc + lq * 4);
      __syncthreads();
      As[lq*4+0][lr] = av.x; As[lq*4+1][lr] = av.y; As[lq*4+2][lr] = av.z; As[lq*4+3][lr] = av.w;
      Bs[lq*4+0][lr] = bv.x; Bs[lq*4+1][lr] = bv.y; Bs[lq*4+2][lr] = bv.z; Bs[lq*4+3][lr] = bv.w;
      __syncthreads();
      MMA_STEP();
    }
  }
  __syncthreads();  // toks visible; As/Bs done

  // Stash pre-activation gates into Gs[g][b_local][kk]
#pragma unroll
  for (int ii = 0; ii < 4; ++ii) {
    int m = ty * 4 + ii;
    int b = b0 + m;
    int tok = toks[m];
#pragma unroll
    for (int jj = 0; jj < 4; ++jj) {
      int c = tx * 4 + jj;
      int g = c >> 4;
      int kk = c & 15;
      int j = g * Hn + k0 + kk;
      float v = acc[ii][jj] + d_embgate[(size_t)tok * G4 + j]
                            + d_encgate[(size_t)b * G4 + j];
      Gs[g][m][kk] = v;
    }
  }
  __syncthreads();

  // LSTM elementwise: 64*16 = 1024 (b,k) cells, 4 per thread
  for (int p = tid; p < 1024; p += 256) {
    int m = p >> 4;
    int kk = p & 15;
    int b = b0 + m;
    int k = k0 + kk;
    float iv = 1.f / (1.f + expf(-Gs[0][m][kk]));
    float fv = 1.f / (1.f + expf(-Gs[1][m][kk]));
    float gv = tanhf(Gs[2][m][kk]);
    float ov = 1.f / (1.f + expf(-Gs[3][m][kk]));
    float cp = (t > 0) ? d_c[(size_t)b * Hn + k] : 0.f;
    float cn = fv * cp + iv * gv;
    d_c[(size_t)b * Hn + k] = cn;
    d_hs[(size_t)t * Bn * Hn + (size_t)b * Hn + k] = ov * tanhf(cn);
  }
}

// ---------------------------------------------------------------------------
// logits[(b*S + s)*V + v] = hs[s][b][:] . out_W[v][:] + out_b[v]
// A row index m = s*256 + b (contiguous in d_hs). M=36096 exact, N=1000 guarded,
// K=512. grid(564,16).
// ---------------------------------------------------------------------------
__global__ __launch_bounds__(256) void out_kernel(
    const float* __restrict__ outW, const float* __restrict__ outb,
    float* __restrict__ out) {
  __shared__ float As[16][64];
  __shared__ float Bs[16][64];
  int tid = threadIdx.x;
  int m0 = blockIdx.x * 64, n0 = blockIdx.y * 64;
  int tx = tid & 15, ty = tid >> 4;
  int lr = tid >> 2, lq = tid & 3;
  float acc[4][4] = {};
  for (int kc = 0; kc < Hn; kc += 16) {
    float4 av = *(const float4*)(d_hs + (size_t)(m0 + lr) * Hn + kc + lq * 4);
    float4 bv = make_float4(0.f, 0.f, 0.f, 0.f);
    if (n0 + lr < Vn)
      bv = *(const float4*)(outW + (size_t)(n0 + lr) * Hn + kc + lq * 4);
    __syncthreads();
    As[lq*4+0][lr] = av.x; As[lq*4+1][lr] = av.y; As[lq*4+2][lr] = av.z; As[lq*4+3][lr] = av.w;
    Bs[lq*4+0][lr] = bv.x; Bs[lq*4+1][lr] = bv.y; Bs[lq*4+2][lr] = bv.z; Bs[lq*4+3][lr] = bv.w;
    __syncthreads();
    MMA_STEP();
  }
#pragma unroll
  for (int ii = 0; ii < 4; ++ii) {
    int m = m0 + ty * 4 + ii;
    int s = m >> 8;          // B = 256
    int b = m & 255;
    size_t obase = ((size_t)b * Sn + s) * Vn;
#pragma unroll
    for (int jj = 0; jj < 4; ++jj) {
      int v = n0 + tx * 4 + jj;
      if (v < Vn) out[obase + v] = acc[ii][jj] + outb[v];
    }
  }
}

extern "C" void kernel_launch(void* const* d_in, const int* in_sizes, int n_in,
                              void* d_out, int out_size) {
  const float* enc  = (const float*)d_in[0];   // [B, E]
  const int*   tgt  = (const int*)  d_in[1];   // [B, S] int32
  const float* emb  = (const float*)d_in[2];   // [V, E]
  const float* Wih  = (const float*)d_in[3];   // [4H, 2E]
  const float* Whh  = (const float*)d_in[4];   // [4H, H]
  const float* bih  = (const float*)d_in[5];   // [4H]
  const float* bhh  = (const float*)d_in[6];   // [4H]
  // d_in[7]=attn_W, d_in[8]=attn_b, d_in[9]=v_w: dead code (softmax over 1 pos)
  const float* outW = (const float*)d_in[10];  // [V, H]
  const float* outb = (const float*)d_in[11];  // [V]
  float* out = (float*)d_out;                  // [B, S, V]

  encgate_kernel<<<dim3(4, 32), 256>>>(enc, Wih, bih, bhh);
  embgate_kernel<<<dim3(16, 32), 256>>>(emb, Wih);
  for (int t = 0; t < Sn; ++t)
    step_kernel<<<dim3(4, 32), 256>>>(Whh, tgt, t);
  out_kernel<<<dim3(564, 16), 256>>>(outW, outb, out);
}

// round 2
// speedup vs baseline: 1.4174x; 1.4174x over previous
#include <cuda_runtime.h>
#include <math.h>
#include <stdint.h>

#define Bn 256
#define Sn 141
#define Vn 1000
#define En 256
#define Hn 512
#define G4 2048   // 4*H
#define VP 1024   // padded vocab for outWT

// ---------------- device scratch (allocation-free rule) ----------------
__device__ float d_embgateP[G4 * Vn];             // [jp][v]  8.2 MB
__device__ float d_encgateP[G4 * Bn];             // [jp][b]  2 MB
__device__ float d_WhhP[Hn * G4];                 // [k][jp]  4 MB
__device__ float d_outWT[Hn * VP];                // [k][v]   2 MB (zero-padded v>=1000)
__device__ float d_hs[(size_t)Sn * Hn * Bn];      // hsT[t][k][b]  74 MB
__device__ float d_c[Hn * Bn];                    // cT[k][b]

// column permutation: j in [0,4H) -> jp so each 64-wide block strip is contiguous
__device__ __forceinline__ int jperm(int j) {
  return ((j & 511) >> 4) * 64 + (j >> 9) * 16 + (j & 15);
}

__device__ __forceinline__ void cp16(uint32_t dst, const void* src) {
  asm volatile("cp.async.cg.shared.global [%0], [%1], 16;" :: "r"(dst), "l"(src));
}
__device__ __forceinline__ void cp_commit() {
  asm volatile("cp.async.commit_group;");
}

#define MMA16(As, Bs) do {                                                       \
    _Pragma("unroll")                                                            \
    for (int kk = 0; kk < 16; ++kk) {                                            \
      float4 a = *(const float4*)&As[kk][ty * 4];                                \
      float4 b = *(const float4*)&Bs[kk][tx * 4];                                \
      acc[0][0] += a.x*b.x; acc[0][1] += a.x*b.y; acc[0][2] += a.x*b.z; acc[0][3] += a.x*b.w; \
      acc[1][0] += a.y*b.x; acc[1][1] += a.y*b.y; acc[1][2] += a.y*b.z; acc[1][3] += a.y*b.w; \
      acc[2][0] += a.z*b.x; acc[2][1] += a.z*b.y; acc[2][2] += a.z*b.z; acc[2][3] += a.z*b.w; \
      acc[3][0] += a.w*b.x; acc[3][1] += a.w*b.y; acc[3][2] += a.w*b.z; acc[3][3] += a.w*b.w; \
    } } while (0)

// 32-deep chunk compute out of double buffer
#define MMA32(buf) do {                                                          \
    _Pragma("unroll")                                                            \
    for (int kk = 0; kk < 32; ++kk) {                                            \
      float4 a = *(const float4*)&As[buf][kk][ty * 4];                           \
      float4 b = *(const float4*)&Bs[buf][kk][tx * 4];                           \
      acc[0][0] += a.x*b.x; acc[0][1] += a.x*b.y; acc[0][2] += a.x*b.z; acc[0][3] += a.x*b.w; \
      acc[1][0] += a.y*b.x; acc[1][1] += a.y*b.y; acc[1][2] += a.y*b.z; acc[1][3] += a.y*b.w; \
      acc[2][0] += a.z*b.x; acc[2][1] += a.z*b.y; acc[2][2] += a.z*b.z; acc[2][3] += a.z*b.w; \
      acc[3][0] += a.w*b.x; acc[3][1] += a.w*b.y; acc[3][2] += a.w*b.z; acc[3][3] += a.w*b.w; \
    } } while (0)

// ---------------------------------------------------------------------------
// One-time transposes
// ---------------------------------------------------------------------------
__global__ void whhT_kernel(const float* __restrict__ Whh) {
  int jp = blockIdx.x * 256 + threadIdx.x;           // grid.x = 8
  int k  = blockIdx.y;                                // grid.y = 512
  int y = jp >> 6, g = (jp >> 4) & 3, kk = jp & 15;
  int j = g * Hn + y * 16 + kk;
  d_WhhP[(size_t)k * G4 + jp] = Whh[(size_t)j * Hn + k];
}

__global__ void outWT_kernel(const float* __restrict__ outW) {
  int v = blockIdx.x * 256 + threadIdx.x;            // grid.x = 4
  int k = blockIdx.y;                                 // grid.y = 512
  d_outWT[(size_t)k * VP + v] = (v < Vn) ? outW[(size_t)v * Hn + k] : 0.f;
}

// ---------------------------------------------------------------------------
// encgateP[jp][b] = enc[b] . W_ih[j][E:2E] + b_ih[j] + b_hh[j]
// ---------------------------------------------------------------------------
__global__ __launch_bounds__(256) void encgate_kernel(
    const float* __restrict__ enc, const float* __restrict__ Wih,
    const float* __restrict__ bih, const float* __restrict__ bhh) {
  __shared__ float As[16][64];
  __shared__ float Bs[16][64];
  int tid = threadIdx.x;
  int m0 = blockIdx.x * 64, n0 = blockIdx.y * 64;
  int tx = tid & 15, ty = tid >> 4;
  int lr = tid >> 2, lq = tid & 3;
  float acc[4][4] = {};
  for (int kc = 0; kc < En; kc += 16) {
    float4 av = *(const float4*)(enc + (size_t)(m0 + lr) * En + kc + lq * 4);
    float4 bv = *(const float4*)(Wih + (size_t)(n0 + lr) * (2 * En) + En + kc + lq * 4);
    __syncthreads();
    As[lq*4+0][lr] = av.x; As[lq*4+1][lr] = av.y; As[lq*4+2][lr] = av.z; As[lq*4+3][lr] = av.w;
    Bs[lq*4+0][lr] = bv.x; Bs[lq*4+1][lr] = bv.y; Bs[lq*4+2][lr] = bv.z; Bs[lq*4+3][lr] = bv.w;
    __syncthreads();
    MMA16(As, Bs);
  }
#pragma unroll
  for (int ii = 0; ii < 4; ++ii) {
    int b = m0 + ty * 4 + ii;
#pragma unroll
    for (int jj = 0; jj < 4; ++jj) {
      int n = n0 + tx * 4 + jj;
      d_encgateP[(size_t)jperm(n) * Bn + b] = acc[ii][jj] + bih[n] + bhh[n];
    }
  }
}

// ---------------------------------------------------------------------------
// embgateP[jp][v] = emb[v] . W_ih[j][0:E]
// ---------------------------------------------------------------------------
__global__ __launch_bounds__(256) void embgate_kernel(
    const float* __restrict__ emb, const float* __restrict__ Wih) {
  __shared__ float As[16][64];
  __shared__ float Bs[16][64];
  int tid = threadIdx.x;
  int m0 = blockIdx.x * 64, n0 = blockIdx.y * 64;
  int tx = tid & 15, ty = tid >> 4;
  int lr = tid >> 2, lq = tid & 3;
  float acc[4][4] = {};
  for (int kc = 0; kc < En; kc += 16) {
    float4 av = make_float4(0.f, 0.f, 0.f, 0.f);
    if (m0 + lr < Vn)
      av = *(const float4*)(emb + (size_t)(m0 + lr) * En + kc + lq * 4);
    float4 bv = *(const float4*)(Wih + (size_t)(n0 + lr) * (2 * En) + kc + lq * 4);
    __syncthreads();
    As[lq*4+0][lr] = av.x; As[lq*4+1][lr] = av.y; As[lq*4+2][lr] = av.z; As[lq*4+3][lr] = av.w;
    Bs[lq*4+0][lr] = bv.x; Bs[lq*4+1][lr] = bv.y; Bs[lq*4+2][lr] = bv.z; Bs[lq*4+3][lr] = bv.w;
    __syncthreads();
    MMA16(As, Bs);
  }
#pragma unroll
  for (int ii = 0; ii < 4; ++ii) {
    int v = m0 + ty * 4 + ii;
    if (v >= Vn) continue;
#pragma unroll
    for (int jj = 0; jj < 4; ++jj) {
      int n = n0 + tx * 4 + jj;
      d_embgateP[(size_t)jperm(n) * Vn + v] = acc[ii][jj];
    }
  }
}

// ---------------------------------------------------------------------------
// Fused LSTM step. gates = hprev @ WhhP (TN) + embgateP[.,tok] + encgateP[.,b];
// elementwise -> hsT[t], cT.  Block: b in [b0,b0+64), jp strip [n0,n0+64)
// (= all 4 gates for k in [k0,k0+16)). grid(4,32), 256 threads.
// cp.async double-buffered, K-chunk = 32.
// ---------------------------------------------------------------------------
__global__ __launch_bounds__(256) void step_kernel(
    const int* __restrict__ tgt, int t) {
  __shared__ __align__(16) float As[2][32][64];
  __shared__ __align__(16) float Bs[2][32][64];
  __shared__ float Gs[64][65];
  __shared__ int toks[64];

  int tid = threadIdx.x;
  int b0 = blockIdx.x * 64;
  int n0 = blockIdx.y * 64;          // jp strip base; k0 = blockIdx.y*16
  int tx = tid & 15, ty = tid >> 4;

  if (tid < 64) toks[tid] = tgt[(size_t)(b0 + tid) * Sn + t];
  __syncthreads();

  // prefetch epilogue addends (hidden under GEMM)
  float addv[4][4];
#pragma unroll
  for (int ii = 0; ii < 4; ++ii) {
    int m = ty * 4 + ii;
    int tok = toks[m];
#pragma unroll
    for (int jj = 0; jj < 4; ++jj) {
      int jp = n0 + tx * 4 + jj;
      addv[ii][jj] = d_embgateP[(size_t)jp * Vn + tok]
                   + d_encgateP[(size_t)jp * Bn + b0 + m];
    }
  }

  float acc[4][4] = {};

  if (t > 0) {
    const float* Aptr = d_hs + (size_t)(t - 1) * Hn * Bn;   // [k][b]
    const float* Bptr = d_WhhP;                              // [k][jp]
    uint32_t sA0 = (uint32_t)__cvta_generic_to_shared(&As[0][0][0]);
    uint32_t sB0 = (uint32_t)__cvta_generic_to_shared(&Bs[0][0][0]);

    int row0 = tid >> 4, seg0 = tid & 15;          // op tid      : rows 0..15
    int row1 = row0 + 16, seg1 = seg0;             // op tid+256  : rows 16..31

#define LOADCHUNK(c, buf) do {                                                   \
      int kc = (c) * 32;                                                         \
      uint32_t dA = sA0 + (buf) * 32 * 64 * 4;                                   \
      uint32_t dB = sB0 + (buf) * 32 * 64 * 4;                                   \
      cp16(dA + (row0 * 64 + seg0 * 4) * 4, Aptr + (size_t)(kc + row0) * Bn + b0 + seg0 * 4); \
      cp16(dA + (row1 * 64 + seg1 * 4) * 4, Aptr + (size_t)(kc + row1) * Bn + b0 + seg1 * 4); \
      cp16(dB + (row0 * 64 + seg0 * 4) * 4, Bptr + (size_t)(kc + row0) * G4 + n0 + seg0 * 4); \
      cp16(dB + (row1 * 64 + seg1 * 4) * 4, Bptr + (size_t)(kc + row1) * G4 + n0 + seg1 * 4); \
      cp_commit();                                                               \
    } while (0)

    LOADCHUNK(0, 0);
    LOADCHUNK(1, 1);
#pragma unroll 1
    for (int c = 0; c < 16; ++c) {
      if (c < 15) asm volatile("cp.async.wait_group 1;");
      else        asm volatile("cp.async.wait_group 0;");
      __syncthreads();
      MMA32(c & 1);
      __syncthreads();
      if (c + 2 < 16) LOADCHUNK(c + 2, c & 1);
    }
#undef LOADCHUNK
  }

  // stage pre-activation gates: Gs[c][m], c = g*16 + kk
#pragma unroll
  for (int ii = 0; ii < 4; ++ii) {
    int m = ty * 4 + ii;
#pragma unroll
    for (int jj = 0; jj < 4; ++jj) {
      int c = tx * 4 + jj;
      Gs[c][m] = acc[ii][jj] + addv[ii][jj];
    }
  }
  __syncthreads();

  // LSTM elementwise: 64 b x 16 k cells
  int k0 = blockIdx.y * 16;
#pragma unroll
  for (int it = 0; it < 4; ++it) {
    int cell = tid + it * 256;
    int m = cell & 63;
    int kk = cell >> 6;
    int kg = k0 + kk;
    int bg = b0 + m;
    float iv = 1.f / (1.f + expf(-Gs[0 * 16 + kk][m]));
    float fv = 1.f / (1.f + expf(-Gs[1 * 16 + kk][m]));
    float gv = tanhf(Gs[2 * 16 + kk][m]);
    float ov = 1.f / (1.f + expf(-Gs[3 * 16 + kk][m]));
    float cp = (t > 0) ? d_c[(size_t)kg * Bn + bg] : 0.f;
    float cn = fv * cp + iv * gv;
    d_c[(size_t)kg * Bn + bg] = cn;
    d_hs[(size_t)t * Hn * Bn + (size_t)kg * Bn + bg] = ov * tanhf(cn);
  }
}

// ---------------------------------------------------------------------------
// logits: C[m=(s,b)][v] = hsT[s][:][b] . outWT[:][v] + outb[v]
// M=36096, N=1024 padded, K=512. grid(564,16), cp.async pipelined.
// ---------------------------------------------------------------------------
__global__ __launch_bounds__(256) void out_kernel(
    const float* __restrict__ outb, float* __restrict__ out) {
  __shared__ __align__(16) float As[2][32][64];
  __shared__ __align__(16) float Bs[2][32][64];
  int tid = threadIdx.x;
  int m0 = blockIdx.x * 64, n0 = blockIdx.y * 64;
  int tx = tid & 15, ty = tid >> 4;

  int s = m0 >> 8;          // 64 | 256 so tile lies in one s
  int bb0 = m0 & 255;

  float bj[4];
#pragma unroll
  for (int jj = 0; jj < 4; ++jj) {
    int v = n0 + tx * 4 + jj;
    bj[jj] = (v < Vn) ? outb[v] : 0.f;
  }

  const float* Aptr = d_hs + (size_t)s * Hn * Bn;   // [k][b]
  const float* Bptr = d_outWT;                      // [k][v]
  uint32_t sA0 = (uint32_t)__cvta_generic_to_shared(&As[0][0][0]);
  uint32_t sB0 = (uint32_t)__cvta_generic_to_shared(&Bs[0][0][0]);
  int row0 = tid >> 4, seg0 = tid & 15;
  int row1 = row0 + 16, seg1 = seg0;

  float acc[4][4] = {};

#define LOADCHUNK(c, buf) do {                                                   \
    int kc = (c) * 32;                                                           \
    uint32_t dA = sA0 + (buf) * 32 * 64 * 4;                                     \
    uint32_t dB = sB0 + (buf) * 32 * 64 * 4;                                     \
    cp16(dA + (row0 * 64 + seg0 * 4) * 4, Aptr + (size_t)(kc + row0) * Bn + bb0 + seg0 * 4); \
    cp16(dA + (row1 * 64 + seg1 * 4) * 4, Aptr + (size_t)(kc + row1) * Bn + bb0 + seg1 * 4); \
    cp16(dB + (row0 * 64 + seg0 * 4) * 4, Bptr + (size_t)(kc + row0) * VP + n0 + seg0 * 4);  \
    cp16(dB + (row1 * 64 + seg1 * 4) * 4, Bptr + (size_t)(kc + row1) * VP + n0 + seg1 * 4);  \
    cp_commit();                                                                 \
  } while (0)

  LOADCHUNK(0, 0);
  LOADCHUNK(1, 1);
#pragma unroll 1
  for (int c = 0; c < 16; ++c) {
    if (c < 15) asm volatile("cp.async.wait_group 1;");
    else        asm volatile("cp.async.wait_group 0;");
    __syncthreads();
    MMA32(c & 1);
    __syncthreads();
    if (c + 2 < 16) LOADCHUNK(c + 2, c & 1);
  }
#undef LOADCHUNK

#pragma unroll
  for (int ii = 0; ii < 4; ++ii) {
    int b = bb0 + ty * 4 + ii;
    size_t obase = ((size_t)b * Sn + s) * Vn;
#pragma unroll
    for (int jj = 0; jj < 4; ++jj) {
      int v = n0 + tx * 4 + jj;
      if (v < Vn) out[obase + v] = acc[ii][jj] + bj[jj];
    }
  }
}

extern "C" void kernel_launch(void* const* d_in, const int* in_sizes, int n_in,
                              void* d_out, int out_size) {
  const float* enc  = (const float*)d_in[0];   // [B, E]
  const int*   tgt  = (const int*)  d_in[1];   // [B, S]
  const float* emb  = (const float*)d_in[2];   // [V, E]
  const float* Wih  = (const float*)d_in[3];   // [4H, 2E]
  const float* Whh  = (const float*)d_in[4];   // [4H, H]
  const float* bih  = (const float*)d_in[5];   // [4H]
  const float* bhh  = (const float*)d_in[6];   // [4H]
  // d_in[7..9] = attn_W, attn_b, v_w : dead (softmax over a single source pos)
  const float* outW = (const float*)d_in[10];  // [V, H]
  const float* outb = (const float*)d_in[11];  // [V]
  float* out = (float*)d_out;                  // [B, S, V]

  whhT_kernel<<<dim3(8, 512), 256>>>(Whh);
  outWT_kernel<<<dim3(4, 512), 256>>>(outW);
  encgate_kernel<<<dim3(4, 32), 256>>>(enc, Wih, bih, bhh);
  embgate_kernel<<<dim3(16, 32), 256>>>(emb, Wih);
  for (int t = 0; t < Sn; ++t)
    step_kernel<<<dim3(4, 32), 256>>>(tgt, t);
  out_kernel<<<dim3(564, 16), 256>>>(outb, out);
}

// round 4
// speedup vs baseline: 1.5246x; 1.0757x over previous
#include <cuda_runtime.h>
#include <cuda_bf16.h>
#include <math.h>
#include <stdint.h>

#define Bn 256
#define Sn 141
#define Vn 1000
#define En 256
#define Hn 512
#define G4 2048   // 4*H
#define VP 1024   // padded vocab

// ---------------- device scratch ----------------
__device__ float d_embgateP[(size_t)Vn * G4];     // [v][jp] fp32
__device__ float d_encgateP[(size_t)Bn * G4];     // [b][jp] fp32
__device__ __nv_bfloat16 d_Whh_hi[(size_t)G4 * Hn];   // [jp][k]
__device__ __nv_bfloat16 d_Whh_lo[(size_t)G4 * Hn];
__device__ __nv_bfloat16 d_outW_hi[(size_t)VP * Hn];  // [v][k], zero-padded
__device__ __nv_bfloat16 d_outW_lo[(size_t)VP * Hn];
__device__ __nv_bfloat16 d_hs_hi[(size_t)Sn * Bn * Hn]; // [t][b][k]
__device__ __nv_bfloat16 d_hs_lo[(size_t)Sn * Bn * Hn];
__device__ float d_c[(size_t)Bn * Hn];                  // [b][k]

// jp mapping: N-block nblk owns 64 cols = 4 gates x 16 k.
// j = g*512 + nblk*16 + kk  ->  jp = nblk*64 + g*16 + kk
__device__ __forceinline__ int jperm(int j) {
  return ((j & 511) >> 4) * 64 + (j >> 9) * 16 + (j & 15);
}

// ---------------- PTX helpers (all plain sm_80+ features) ----------------
__device__ __forceinline__ void cp16(uint32_t dst, const void* src) {
  asm volatile("cp.async.cg.shared.global [%0], [%1], 16;" :: "r"(dst), "l"(src));
}
__device__ __forceinline__ void cp_commit() { asm volatile("cp.async.commit_group;"); }
__device__ __forceinline__ void cp_wait1() { asm volatile("cp.async.wait_group 1;" ::: "memory"); }
__device__ __forceinline__ void cp_wait0() { asm volatile("cp.async.wait_group 0;" ::: "memory"); }

__device__ __forceinline__ void ldm4(uint32_t& r0, uint32_t& r1, uint32_t& r2, uint32_t& r3,
                                     uint32_t addr) {
  asm volatile("ldmatrix.sync.aligned.m8n8.x4.shared.b16 {%0,%1,%2,%3}, [%4];"
               : "=r"(r0), "=r"(r1), "=r"(r2), "=r"(r3) : "r"(addr));
}
__device__ __forceinline__ void mma16816(float* d, const uint32_t* a, uint32_t b0, uint32_t b1) {
  asm volatile(
    "mma.sync.aligned.m16n8k16.row.col.f32.bf16.bf16.f32 "
    "{%0,%1,%2,%3}, {%4,%5,%6,%7}, {%8,%9}, {%0,%1,%2,%3};"
    : "+f"(d[0]), "+f"(d[1]), "+f"(d[2]), "+f"(d[3])
    : "r"(a[0]), "r"(a[1]), "r"(a[2]), "r"(a[3]), "r"(b0), "r"(b1));
}

// smem layout (bytes). Per buffer: Ahi 16K, Alo 16K, Bhi 8K, Blo 8K = 48K.
#define STG      49152
#define AHI_OFF  0
#define ALO_OFF  16384
#define BHI_OFF  32768
#define BLO_OFF  40960
#define ADD_EMB  98304                       // [128][64] f32 = 32K
#define ADD_ENC  131072                      // [128][64] f32 = 32K
#define GS_OFF   163840                      // [128][68] f32 = 34816
#define GS_STRIDE 68
#define STEP_SMEM 198656
#define OUT_SMEM  98304

// ---------------------------------------------------------------------------
// prep: Whh fp32 -> bf16 hi/lo, row-permuted [jp][k]
// ---------------------------------------------------------------------------
__global__ void prep_whh(const float* __restrict__ Whh) {
  int idx = blockIdx.x * 256 + threadIdx.x;       // 4H*H = 1048576
  int j = idx >> 9, k = idx & 511;
  int jp = jperm(j);
  float x = Whh[idx];
  __nv_bfloat16 hi = __float2bfloat16(x);
  __nv_bfloat16 lo = __float2bfloat16(x - __bfloat162float(hi));
  d_Whh_hi[(size_t)jp * Hn + k] = hi;
  d_Whh_lo[(size_t)jp * Hn + k] = lo;
}

__global__ void prep_outw(const float* __restrict__ outW) {
  int idx = blockIdx.x * 256 + threadIdx.x;       // 1024*512
  int v = idx >> 9, k = idx & 511;
  float x = (v < Vn) ? outW[(size_t)v * Hn + k] : 0.f;
  __nv_bfloat16 hi = __float2bfloat16(x);
  __nv_bfloat16 lo = __float2bfloat16(x - __bfloat162float(hi));
  d_outW_hi[idx] = hi;
  d_outW_lo[idx] = lo;
}

// ---------------------------------------------------------------------------
// fp32 prep GEMMs (small, run once)
// ---------------------------------------------------------------------------
#define MMA16(As, Bs) do {                                                       \
    _Pragma("unroll")                                                            \
    for (int kk = 0; kk < 16; ++kk) {                                            \
      float4 a = *(const float4*)&As[kk][ty * 4];                                \
      float4 b = *(const float4*)&Bs[kk][tx * 4];                                \
      acc[0][0] += a.x*b.x; acc[0][1] += a.x*b.y; acc[0][2] += a.x*b.z; acc[0][3] += a.x*b.w; \
      acc[1][0] += a.y*b.x; acc[1][1] += a.y*b.y; acc[1][2] += a.y*b.z; acc[1][3] += a.y*b.w; \
      acc[2][0] += a.z*b.x; acc[2][1] += a.z*b.y; acc[2][2] += a.z*b.z; acc[2][3] += a.z*b.w; \
      acc[3][0] += a.w*b.x; acc[3][1] += a.w*b.y; acc[3][2] += a.w*b.z; acc[3][3] += a.w*b.w; \
    } } while (0)

__global__ __launch_bounds__(256) void encgate_kernel(
    const float* __restrict__ enc, const float* __restrict__ Wih,
    const float* __restrict__ bih, const float* __restrict__ bhh) {
  __shared__ float As[16][64];
  __shared__ float Bs[16][64];
  int tid = threadIdx.x;
  int m0 = blockIdx.x * 64, n0 = blockIdx.y * 64;
  int tx = tid & 15, ty = tid >> 4;
  int lr = tid >> 2, lq = tid & 3;
  float acc[4][4] = {};
  for (int kc = 0; kc < En; kc += 16) {
    float4 av = *(const float4*)(enc + (size_t)(m0 + lr) * En + kc + lq * 4);
    float4 bv = *(const float4*)(Wih + (size_t)(n0 + lr) * (2 * En) + En + kc + lq * 4);
    __syncthreads();
    As[lq*4+0][lr] = av.x; As[lq*4+1][lr] = av.y; As[lq*4+2][lr] = av.z; As[lq*4+3][lr] = av.w;
    Bs[lq*4+0][lr] = bv.x; Bs[lq*4+1][lr] = bv.y; Bs[lq*4+2][lr] = bv.z; Bs[lq*4+3][lr] = bv.w;
    __syncthreads();
    MMA16(As, Bs);
  }
#pragma unroll
  for (int ii = 0; ii < 4; ++ii) {
    int b = m0 + ty * 4 + ii;
#pragma unroll
    for (int jj = 0; jj < 4; ++jj) {
      int n = n0 + tx * 4 + jj;
      d_encgateP[(size_t)b * G4 + jperm(n)] = acc[ii][jj] + bih[n] + bhh[n];
    }
  }
}

__global__ __launch_bounds__(256) void embgate_kernel(
    const float* __restrict__ emb, const float* __restrict__ Wih) {
  __shared__ float As[16][64];
  __shared__ float Bs[16][64];
  int tid = threadIdx.x;
  int m0 = blockIdx.x * 64, n0 = blockIdx.y * 64;
  int tx = tid & 15, ty = tid >> 4;
  int lr = tid >> 2, lq = tid & 3;
  float acc[4][4] = {};
  for (int kc = 0; kc < En; kc += 16) {
    float4 av = make_float4(0.f, 0.f, 0.f, 0.f);
    if (m0 + lr < Vn)
      av = *(const float4*)(emb + (size_t)(m0 + lr) * En + kc + lq * 4);
    float4 bv = *(const float4*)(Wih + (size_t)(n0 + lr) * (2 * En) + kc + lq * 4);
    __syncthreads();
    As[lq*4+0][lr] = av.x; As[lq*4+1][lr] = av.y; As[lq*4+2][lr] = av.z; As[lq*4+3][lr] = av.w;
    Bs[lq*4+0][lr] = bv.x; Bs[lq*4+1][lr] = bv.y; Bs[lq*4+2][lr] = bv.z; Bs[lq*4+3][lr] = bv.w;
    __syncthreads();
    MMA16(As, Bs);
  }
#pragma unroll
  for (int ii = 0; ii < 4; ++ii) {
    int v = m0 + ty * 4 + ii;
    if (v >= Vn) continue;
#pragma unroll
    for (int jj = 0; jj < 4; ++jj) {
      int n = n0 + tx * 4 + jj;
      d_embgateP[(size_t)v * G4 + jperm(n)] = acc[ii][jj];
    }
  }
}

// ============================================================================
// Shared GEMM-chunk machinery (warp mma, 128x64 CTA tile, K-chunk 64,
// double-buffered cp.async, SW-xor swizzled smem rows of 128B)
// ============================================================================

// Per-chunk load: A rows 128 (hi+lo), B rows 64 (hi+lo). 256 threads.
#define LOADC_GEN(c, buf, AhiP, AloP, BhiP, BloP)  do {                          \
    int kc = (c) * 64;                                                           \
    uint32_t st = su + (buf) * STG;                                              \
    {                                                                            \
      int rowA = tid >> 1;                                                       \
      int sg0 = (tid & 1) * 4;                                                   \
      uint32_t dA = st + rowA * 128;                                             \
      uint32_t swA = (uint32_t)(rowA & 7) * 16;                                  \
      _Pragma("unroll")                                                          \
      for (int q = 0; q < 4; ++q) {                                              \
        int sg = sg0 + q;                                                        \
        uint32_t so = ((uint32_t)(sg * 16)) ^ swA;                               \
        cp16(dA + AHI_OFF + so, (AhiP) + (size_t)rowA * Hn + kc + sg * 8);       \
        cp16(dA + ALO_OFF + so, (AloP) + (size_t)rowA * Hn + kc + sg * 8);       \
      }                                                                          \
    }                                                                            \
    {                                                                            \
      int rB = tid >> 2;                                                         \
      int sg0 = (tid & 3) * 2;                                                   \
      uint32_t dB = st + rB * 128;                                               \
      uint32_t swB = (uint32_t)(rB & 7) * 16;                                    \
      _Pragma("unroll")                                                          \
      for (int q = 0; q < 2; ++q) {                                              \
        int sg = sg0 + q;                                                        \
        uint32_t so = ((uint32_t)(sg * 16)) ^ swB;                               \
        cp16(dB + BHI_OFF + so, (BhiP) + (size_t)rB * Hn + kc + sg * 8);         \
        cp16(dB + BLO_OFF + so, (BloP) + (size_t)rB * Hn + kc + sg * 8);         \
      }                                                                          \
    }                                                                            \
    cp_commit();                                                                 \
  } while (0)

// Compute one 64-deep chunk from buffer `buf` into acc[2][4][4].
// Warp layout: wm in [0,4) rows 32 each; wn in [0,2) cols 32 each.
__device__ __forceinline__ void compute_chunk(
    float acc[2][4][4], uint32_t su, int buf, int wm, int wn, int lane) {
  uint32_t base = su + buf * STG;
  int lr = lane & 7;
  int sel = lane >> 3;
  int a_roff = (sel & 1) * 8;
  int a_koff = (sel & 2) * 8;          // +16 bytes if sel>=2
  int b_koff = (sel & 1) * 16;
  int b_roff = (sel & 2) * 4;          // +8 rows if sel>=2
  uint32_t swm = (uint32_t)(lr * 16);

#pragma unroll
  for (int ks = 0; ks < 4; ++ks) {
    int kb = ks * 32;
    uint32_t ah[2][4], al[2][4], bh[2][4], bl[2][4];
#pragma unroll
    for (int i = 0; i < 2; ++i) {
      int row = wm * 32 + i * 16 + lr + a_roff;
      uint32_t off = (uint32_t)row * 128 + (((uint32_t)(kb + a_koff)) ^ swm);
      ldm4(ah[i][0], ah[i][1], ah[i][2], ah[i][3], base + AHI_OFF + off);
      ldm4(al[i][0], al[i][1], al[i][2], al[i][3], base + ALO_OFF + off);
    }
#pragma unroll
    for (int p = 0; p < 2; ++p) {
      int row = wn * 32 + p * 16 + lr + b_roff;
      uint32_t off = (uint32_t)row * 128 + (((uint32_t)(kb + b_koff)) ^ swm);
      ldm4(bh[p][0], bh[p][1], bh[p][2], bh[p][3], base + BHI_OFF + off);
      ldm4(bl[p][0], bl[p][1], bl[p][2], bl[p][3], base + BLO_OFF + off);
    }
#pragma unroll
    for (int i = 0; i < 2; ++i) {
#pragma unroll
      for (int nt = 0; nt < 4; ++nt) {
        int p = nt >> 1, q = (nt & 1) * 2;
        mma16816(acc[i][nt], ah[i], bh[p][q], bh[p][q + 1]);
        mma16816(acc[i][nt], ah[i], bl[p][q], bl[p][q + 1]);
        mma16816(acc[i][nt], al[i], bh[p][q], bh[p][q + 1]);
      }
    }
  }
}

// ---------------------------------------------------------------------------
// LSTM step. grid(2,32), 256 threads.
// D[128 b-rows, 64 cols=(4 gates x 16 k)] = h_{t-1} @ WhhP^T (bf16x3)
// ---------------------------------------------------------------------------
__global__ __launch_bounds__(256, 1) void step_mma(const int* __restrict__ tgt, int t) {
  extern __shared__ __align__(1024) char smem[];
  uint32_t su = (uint32_t)__cvta_generic_to_shared(smem);
  int tid = threadIdx.x;
  int lane = tid & 31, wid = tid >> 5;
  int wm = wid >> 1, wn = wid & 1;
  int m0 = blockIdx.x * 128;
  int nblk = blockIdx.y;
  int n0 = nblk * 64;

  // addend prefetch (group 0)
  {
    int r = tid >> 1;
    int half = (tid & 1) * 32;
    int tok = tgt[(size_t)(m0 + r) * Sn + t];
    const float* se = d_embgateP + (size_t)tok * G4 + n0 + half;
    const float* sc = d_encgateP + (size_t)(m0 + r) * G4 + n0 + half;
    uint32_t de = su + ADD_EMB + (r * 64 + half) * 4;
    uint32_t dc = su + ADD_ENC + (r * 64 + half) * 4;
#pragma unroll
    for (int q = 0; q < 8; ++q) {
      cp16(de + q * 16, se + q * 4);
      cp16(dc + q * 16, sc + q * 4);
    }
    cp_commit();
  }

  float acc[2][4][4] = {};

  if (t > 0) {
    const __nv_bfloat16* Ahi = d_hs_hi + ((size_t)(t - 1) * Bn + m0) * Hn;
    const __nv_bfloat16* Alo = d_hs_lo + ((size_t)(t - 1) * Bn + m0) * Hn;
    const __nv_bfloat16* Bhi = d_Whh_hi + (size_t)n0 * Hn;
    const __nv_bfloat16* Blo = d_Whh_lo + (size_t)n0 * Hn;

    LOADC_GEN(0, 0, Ahi, Alo, Bhi, Blo);
    LOADC_GEN(1, 1, Ahi, Alo, Bhi, Blo);
#pragma unroll 1
    for (int c = 0; c < 8; ++c) {
      if (c < 7) cp_wait1(); else cp_wait0();
      __syncthreads();
      compute_chunk(acc, su, c & 1, wm, wn, lane);
      __syncthreads();
      if (c + 2 < 8) LOADC_GEN(c + 2, c & 1, Ahi, Alo, Bhi, Blo);
    }

    // stage accum to Gs[row][col]
    float* Gs = (float*)(smem + GS_OFF);
    int r0 = (lane >> 2), c0 = (lane & 3) * 2;
#pragma unroll
    for (int i = 0; i < 2; ++i) {
#pragma unroll
      for (int nt = 0; nt < 4; ++nt) {
        int row = wm * 32 + i * 16 + r0;
        int col = wn * 32 + nt * 8 + c0;
        Gs[row * GS_STRIDE + col]             = acc[i][nt][0];
        Gs[row * GS_STRIDE + col + 1]         = acc[i][nt][1];
        Gs[(row + 8) * GS_STRIDE + col]       = acc[i][nt][2];
        Gs[(row + 8) * GS_STRIDE + col + 1]   = acc[i][nt][3];
      }
    }
  } else {
    cp_wait0();
  }
  __syncthreads();

  // ---- fused LSTM elementwise: thread -> row m=tid>>1, kk in [(tid&1)*8, +8)
  const float* Gs = (const float*)(smem + GS_OFF);
  int m = tid >> 1;
  int kk0 = (tid & 1) * 8;
  const float* aE = (const float*)(smem + ADD_EMB) + m * 64;
  const float* aC = (const float*)(smem + ADD_ENC) + m * 64;
  int b = m0 + m;
  int kbase = nblk * 16 + kk0;

  float cprev[8];
  if (t > 0) {
    const float4* c4 = (const float4*)(d_c + (size_t)b * Hn + kbase);
    float4 v0 = c4[0], v1 = c4[1];
    cprev[0]=v0.x; cprev[1]=v0.y; cprev[2]=v0.z; cprev[3]=v0.w;
    cprev[4]=v1.x; cprev[5]=v1.y; cprev[6]=v1.z; cprev[7]=v1.w;
  } else {
#pragma unroll
    for (int q = 0; q < 8; ++q) cprev[q] = 0.f;
  }

  float cn[8];
  __nv_bfloat16 hhi[8], hlo[8];
#pragma unroll
  for (int q = 0; q < 8; ++q) {
    int kk = kk0 + q;
    float gi = aE[kk]      + aC[kk];
    float gf = aE[16 + kk] + aC[16 + kk];
    float gg = aE[32 + kk] + aC[32 + kk];
    float go = aE[48 + kk] + aC[48 + kk];
    if (t > 0) {
      gi += Gs[m * GS_STRIDE + kk];
      gf += Gs[m * GS_STRIDE + 16 + kk];
      gg += Gs[m * GS_STRIDE + 32 + kk];
      go += Gs[m * GS_STRIDE + 48 + kk];
    }
    float iv = 1.f / (1.f + expf(-gi));
    float fv = 1.f / (1.f + expf(-gf));
    float gv = tanhf(gg);
    float ov = 1.f / (1.f + expf(-go));
    float cc = fv * cprev[q] + iv * gv;
    cn[q] = cc;
    float hv = ov * tanhf(cc);
    __nv_bfloat16 hi = __float2bfloat16(hv);
    hhi[q] = hi;
    hlo[q] = __float2bfloat16(hv - __bfloat162float(hi));
  }
  {
    float4* c4 = (float4*)(d_c + (size_t)b * Hn + kbase);
    c4[0] = make_float4(cn[0], cn[1], cn[2], cn[3]);
    c4[1] = make_float4(cn[4], cn[5], cn[6], cn[7]);
    size_t hoff = ((size_t)t * Bn + b) * Hn + kbase;
    *(uint4*)(d_hs_hi + hoff) = *(const uint4*)hhi;
    *(uint4*)(d_hs_lo + hoff) = *(const uint4*)hlo;
  }
}

// ---------------------------------------------------------------------------
// Output GEMM. grid(282,16), 256 threads. rows m = t*256+b, cols v.
// ---------------------------------------------------------------------------
__global__ __launch_bounds__(256, 2) void out_mma(const float* __restrict__ outb,
                                                  float* __restrict__ out) {
  extern __shared__ __align__(1024) char smem[];
  uint32_t su = (uint32_t)__cvta_generic_to_shared(smem);
  int tid = threadIdx.x;
  int lane = tid & 31, wid = tid >> 5;
  int wm = wid >> 1, wn = wid & 1;
  int m0 = blockIdx.x * 128;
  int n0 = blockIdx.y * 64;

  const __nv_bfloat16* Ahi = d_hs_hi + (size_t)m0 * Hn;
  const __nv_bfloat16* Alo = d_hs_lo + (size_t)m0 * Hn;
  const __nv_bfloat16* Bhi = d_outW_hi + (size_t)n0 * Hn;
  const __nv_bfloat16* Blo = d_outW_lo + (size_t)n0 * Hn;

  float acc[2][4][4] = {};
  LOADC_GEN(0, 0, Ahi, Alo, Bhi, Blo);
  LOADC_GEN(1, 1, Ahi, Alo, Bhi, Blo);
#pragma unroll 1
  for (int c = 0; c < 8; ++c) {
    if (c < 7) cp_wait1(); else cp_wait0();
    __syncthreads();
    compute_chunk(acc, su, c & 1, wm, wn, lane);
    __syncthreads();
    if (c + 2 < 8) LOADC_GEN(c + 2, c & 1, Ahi, Alo, Bhi, Blo);
  }

  // epilogue straight from fragments
  int r0 = lane >> 2, c0 = (lane & 3) * 2;
#pragma unroll
  for (int nt = 0; nt < 4; ++nt) {
    int v = n0 + wn * 32 + nt * 8 + c0;
    if (v >= Vn) continue;
    float b0 = outb[v], b1 = outb[v + 1];
#pragma unroll
    for (int i = 0; i < 2; ++i) {
      int mrow = m0 + wm * 32 + i * 16 + r0;
#pragma unroll
      for (int h = 0; h < 2; ++h) {
        int m = mrow + h * 8;
        int s = m >> 8, bb = m & 255;
        float* dst = out + ((size_t)bb * Sn + s) * Vn + v;
        float2 o;
        o.x = acc[i][nt][h * 2 + 0] + b0;
        o.y = acc[i][nt][h * 2 + 1] + b1;
        *(float2*)dst = o;
      }
    }
  }
}

extern "C" void kernel_launch(void* const* d_in, const int* in_sizes, int n_in,
                              void* d_out, int out_size) {
  const float* enc  = (const float*)d_in[0];
  const int*   tgt  = (const int*)  d_in[1];
  const float* emb  = (const float*)d_in[2];
  const float* Wih  = (const float*)d_in[3];
  const float* Whh  = (const float*)d_in[4];
  const float* bih  = (const float*)d_in[5];
  const float* bhh  = (const float*)d_in[6];
  // d_in[7..9] = attn_W, attn_b, v_w : dead (softmax over single source pos)
  const float* outW = (const float*)d_in[10];
  const float* outb = (const float*)d_in[11];
  float* out = (float*)d_out;

  cudaFuncSetAttribute(step_mma, cudaFuncAttributeMaxDynamicSharedMemorySize, STEP_SMEM);
  cudaFuncSetAttribute(out_mma,  cudaFuncAttributeMaxDynamicSharedMemorySize, OUT_SMEM);

  prep_whh<<<4096, 256>>>(Whh);
  prep_outw<<<2048, 256>>>(outW);
  encgate_kernel<<<dim3(4, 32), 256>>>(enc, Wih, bih, bhh);
  embgate_kernel<<<dim3(16, 32), 256>>>(emb, Wih);
  for (int t = 0; t < Sn; ++t)
    step_mma<<<dim3(2, 32), 256, STEP_SMEM>>>(tgt, t);
  out_mma<<<dim3(282, 16), 256, OUT_SMEM>>>(outb, out);
}

// round 5
// speedup vs baseline: 1.7832x; 1.1696x over previous
#include <cuda_runtime.h>
#include <cuda_bf16.h>
#include <math.h>
#include <stdint.h>

#define Bn 256
#define Sn 141
#define Vn 1000
#define En 256
#define Hn 512
#define G4 2048   // 4*H
#define VP 1024   // padded vocab

#define NC_STEP 64          // recurrence CTAs
#define NCTA    148         // total persistent CTAs (1/SM)
#define NOUT    (Sn * 32)   // out tiles: per t, 2 m-tiles x 16 n-tiles

// ---------------- device scratch ----------------
__device__ float d_embgateP[(size_t)Vn * G4];     // [v][jp] fp32
__device__ float d_encgateP[(size_t)Bn * G4];     // [b][jp] fp32
__device__ __nv_bfloat16 d_Whh_hi[(size_t)G4 * Hn];   // [jp][k]
__device__ __nv_bfloat16 d_Whh_lo[(size_t)G4 * Hn];
__device__ __nv_bfloat16 d_outW_hi[(size_t)VP * Hn];  // [v][k], zero-padded
__device__ __nv_bfloat16 d_outW_lo[(size_t)VP * Hn];
__device__ __nv_bfloat16 d_hs_hi[(size_t)Sn * Bn * Hn]; // [t][b][k]
__device__ __nv_bfloat16 d_hs_lo[(size_t)Sn * Bn * Hn];

// sync state (reset each replay by reset_k)
__device__ unsigned d_count;
__device__ unsigned d_sense;
__device__ unsigned d_wq;

__device__ __forceinline__ int jperm(int j) {
  return ((j & 511) >> 4) * 64 + (j >> 9) * 16 + (j & 15);
}

// ---------------- PTX helpers (plain sm_80+ features only) ----------------
__device__ __forceinline__ void cp16(uint32_t dst, const void* src) {
  asm volatile("cp.async.cg.shared.global [%0], [%1], 16;" :: "r"(dst), "l"(src));
}
__device__ __forceinline__ void cp_commit() { asm volatile("cp.async.commit_group;"); }
__device__ __forceinline__ void cp_wait1() { asm volatile("cp.async.wait_group 1;" ::: "memory"); }
__device__ __forceinline__ void cp_wait0() { asm volatile("cp.async.wait_group 0;" ::: "memory"); }

__device__ __forceinline__ void ldm4(uint32_t& r0, uint32_t& r1, uint32_t& r2, uint32_t& r3,
                                     uint32_t addr) {
  asm volatile("ldmatrix.sync.aligned.m8n8.x4.shared.b16 {%0,%1,%2,%3}, [%4];"
               : "=r"(r0), "=r"(r1), "=r"(r2), "=r"(r3) : "r"(addr));
}
__device__ __forceinline__ void mma16816(float* d, const uint32_t* a, uint32_t b0, uint32_t b1) {
  asm volatile(
    "mma.sync.aligned.m16n8k16.row.col.f32.bf16.bf16.f32 "
    "{%0,%1,%2,%3}, {%4,%5,%6,%7}, {%8,%9}, {%0,%1,%2,%3};"
    : "+f"(d[0]), "+f"(d[1]), "+f"(d[2]), "+f"(d[3])
    : "r"(a[0]), "r"(a[1]), "r"(a[2]), "r"(a[3]), "r"(b0), "r"(b1));
}
__device__ __forceinline__ unsigned ld_acq(unsigned* p) {
  unsigned v;
  asm volatile("ld.acquire.gpu.u32 %0, [%1];" : "=r"(v) : "l"(p) : "memory");
  return v;
}

// smem layout (bytes). Per buffer: Ahi 16K, Alo 16K, Bhi 8K, Blo 8K = 48K.
#define STG      49152
#define AHI_OFF  0
#define ALO_OFF  16384
#define BHI_OFF  32768
#define BLO_OFF  40960
#define ADD_EMB  98304                       // [128][64] f32 = 32K (per step)
#define ADD_ENC  131072                      // [128][64] f32 = 32K (resident)
#define GS_OFF   163840                      // [128][68] f32
#define GS_STRIDE 68
#define FUSED_SMEM 198656

// ---------------------------------------------------------------------------
__global__ void reset_k() { d_count = 0; d_sense = 0; d_wq = 0; }

__global__ void prep_whh(const float* __restrict__ Whh) {
  int idx = blockIdx.x * 256 + threadIdx.x;       // 4H*H = 1048576
  int j = idx >> 9, k = idx & 511;
  int jp = jperm(j);
  float x = Whh[idx];
  __nv_bfloat16 hi = __float2bfloat16(x);
  __nv_bfloat16 lo = __float2bfloat16(x - __bfloat162float(hi));
  d_Whh_hi[(size_t)jp * Hn + k] = hi;
  d_Whh_lo[(size_t)jp * Hn + k] = lo;
}

__global__ void prep_outw(const float* __restrict__ outW) {
  int idx = blockIdx.x * 256 + threadIdx.x;       // 1024*512
  int v = idx >> 9, k = idx & 511;
  float x = (v < Vn) ? outW[(size_t)v * Hn + k] : 0.f;
  __nv_bfloat16 hi = __float2bfloat16(x);
  __nv_bfloat16 lo = __float2bfloat16(x - __bfloat162float(hi));
  d_outW_hi[idx] = hi;
  d_outW_lo[idx] = lo;
}

// ---------------------------------------------------------------------------
// fp32 prep GEMMs (run once)
// ---------------------------------------------------------------------------
#define MMA16(As, Bs) do {                                                       \
    _Pragma("unroll")                                                            \
    for (int kk = 0; kk < 16; ++kk) {                                            \
      float4 a = *(const float4*)&As[kk][ty * 4];                                \
      float4 b = *(const float4*)&Bs[kk][tx * 4];                                \
      acc[0][0] += a.x*b.x; acc[0][1] += a.x*b.y; acc[0][2] += a.x*b.z; acc[0][3] += a.x*b.w; \
      acc[1][0] += a.y*b.x; acc[1][1] += a.y*b.y; acc[1][2] += a.y*b.z; acc[1][3] += a.y*b.w; \
      acc[2][0] += a.z*b.x; acc[2][1] += a.z*b.y; acc[2][2] += a.z*b.z; acc[2][3] += a.z*b.w; \
      acc[3][0] += a.w*b.x; acc[3][1] += a.w*b.y; acc[3][2] += a.w*b.z; acc[3][3] += a.w*b.w; \
    } } while (0)

__global__ __launch_bounds__(256) void encgate_kernel(
    const float* __restrict__ enc, const float* __restrict__ Wih,
    const float* __restrict__ bih, const float* __restrict__ bhh) {
  __shared__ float As[16][64];
  __shared__ float Bs[16][64];
  int tid = threadIdx.x;
  int m0 = blockIdx.x * 64, n0 = blockIdx.y * 64;
  int tx = tid & 15, ty = tid >> 4;
  int lr = tid >> 2, lq = tid & 3;
  float acc[4][4] = {};
  for (int kc = 0; kc < En; kc += 16) {
    float4 av = *(const float4*)(enc + (size_t)(m0 + lr) * En + kc + lq * 4);
    float4 bv = *(const float4*)(Wih + (size_t)(n0 + lr) * (2 * En) + En + kc + lq * 4);
    __syncthreads();
    As[lq*4+0][lr] = av.x; As[lq*4+1][lr] = av.y; As[lq*4+2][lr] = av.z; As[lq*4+3][lr] = av.w;
    Bs[lq*4+0][lr] = bv.x; Bs[lq*4+1][lr] = bv.y; Bs[lq*4+2][lr] = bv.z; Bs[lq*4+3][lr] = bv.w;
    __syncthreads();
    MMA16(As, Bs);
  }
#pragma unroll
  for (int ii = 0; ii < 4; ++ii) {
    int b = m0 + ty * 4 + ii;
#pragma unroll
    for (int jj = 0; jj < 4; ++jj) {
      int n = n0 + tx * 4 + jj;
      d_encgateP[(size_t)b * G4 + jperm(n)] = acc[ii][jj] + bih[n] + bhh[n];
    }
  }
}

__global__ __launch_bounds__(256) void embgate_kernel(
    const float* __restrict__ emb, const float* __restrict__ Wih) {
  __shared__ float As[16][64];
  __shared__ float Bs[16][64];
  int tid = threadIdx.x;
  int m0 = blockIdx.x * 64, n0 = blockIdx.y * 64;
  int tx = tid & 15, ty = tid >> 4;
  int lr = tid >> 2, lq = tid & 3;
  float acc[4][4] = {};
  for (int kc = 0; kc < En; kc += 16) {
    float4 av = make_float4(0.f, 0.f, 0.f, 0.f);
    if (m0 + lr < Vn)
      av = *(const float4*)(emb + (size_t)(m0 + lr) * En + kc + lq * 4);
    float4 bv = *(const float4*)(Wih + (size_t)(n0 + lr) * (2 * En) + kc + lq * 4);
    __syncthreads();
    As[lq*4+0][lr] = av.x; As[lq*4+1][lr] = av.y; As[lq*4+2][lr] = av.z; As[lq*4+3][lr] = av.w;
    Bs[lq*4+0][lr] = bv.x; Bs[lq*4+1][lr] = bv.y; Bs[lq*4+2][lr] = bv.z; Bs[lq*4+3][lr] = bv.w;
    __syncthreads();
    MMA16(As, Bs);
  }
#pragma unroll
  for (int ii = 0; ii < 4; ++ii) {
    int v = m0 + ty * 4 + ii;
    if (v >= Vn) continue;
#pragma unroll
    for (int jj = 0; jj < 4; ++jj) {
      int n = n0 + tx * 4 + jj;
      d_embgateP[(size_t)v * G4 + jperm(n)] = acc[ii][jj];
    }
  }
}

// ============================================================================
// Shared GEMM-chunk machinery (warp mma, 128x64 CTA tile, K-chunk 64)
// ============================================================================
#define LOADC_GEN(c, buf, AhiP, AloP, BhiP, BloP)  do {                          \
    int kc = (c) * 64;                                                           \
    uint32_t st = su + (buf) * STG;                                              \
    {                                                                            \
      int rowA = tid >> 1;                                                       \
      int sg0 = (tid & 1) * 4;                                                   \
      uint32_t dA = st + rowA * 128;                                             \
      uint32_t swA = (uint32_t)(rowA & 7) * 16;                                  \
      _Pragma("unroll")                                                          \
      for (int q = 0; q < 4; ++q) {                                              \
        int sg = sg0 + q;                                                        \
        uint32_t so = ((uint32_t)(sg * 16)) ^ swA;                               \
        cp16(dA + AHI_OFF + so, (AhiP) + (size_t)rowA * Hn + kc + sg * 8);       \
        cp16(dA + ALO_OFF + so, (AloP) + (size_t)rowA * Hn + kc + sg * 8);       \
      }                                                                          \
    }                                                                            \
    {                                                                            \
      int rB = tid >> 2;                                                         \
      int sg0 = (tid & 3) * 2;                                                   \
      uint32_t dB = st + rB * 128;                                               \
      uint32_t swB = (uint32_t)(rB & 7) * 16;                                    \
      _Pragma("unroll")                                                          \
      for (int q = 0; q < 2; ++q) {                                              \
        int sg = sg0 + q;                                                        \
        uint32_t so = ((uint32_t)(sg * 16)) ^ swB;                               \
        cp16(dB + BHI_OFF + so, (BhiP) + (size_t)rB * Hn + kc + sg * 8);         \
        cp16(dB + BLO_OFF + so, (BloP) + (size_t)rB * Hn + kc + sg * 8);         \
      }                                                                          \
    }                                                                            \
    cp_commit();                                                                 \
  } while (0)

__device__ __forceinline__ void compute_chunk(
    float acc[2][4][4], uint32_t su, int buf, int wm, int wn, int lane) {
  uint32_t base = su + buf * STG;
  int lr = lane & 7;
  int sel = lane >> 3;
  int a_roff = (sel & 1) * 8;
  int a_koff = (sel & 2) * 8;
  int b_koff = (sel & 1) * 16;
  int b_roff = (sel & 2) * 4;
  uint32_t swm = (uint32_t)(lr * 16);

#pragma unroll
  for (int ks = 0; ks < 4; ++ks) {
    int kb = ks * 32;
    uint32_t ah[2][4], al[2][4], bh[2][4], bl[2][4];
#pragma unroll
    for (int i = 0; i < 2; ++i) {
      int row = wm * 32 + i * 16 + lr + a_roff;
      uint32_t off = (uint32_t)row * 128 + (((uint32_t)(kb + a_koff)) ^ swm);
      ldm4(ah[i][0], ah[i][1], ah[i][2], ah[i][3], base + AHI_OFF + off);
      ldm4(al[i][0], al[i][1], al[i][2], al[i][3], base + ALO_OFF + off);
    }
#pragma unroll
    for (int p = 0; p < 2; ++p) {
      int row = wn * 32 + p * 16 + lr + b_roff;
      uint32_t off = (uint32_t)row * 128 + (((uint32_t)(kb + b_koff)) ^ swm);
      ldm4(bh[p][0], bh[p][1], bh[p][2], bh[p][3], base + BHI_OFF + off);
      ldm4(bl[p][0], bl[p][1], bl[p][2], bl[p][3], base + BLO_OFF + off);
    }
#pragma unroll
    for (int i = 0; i < 2; ++i) {
#pragma unroll
      for (int nt = 0; nt < 4; ++nt) {
        int p = nt >> 1, q = (nt & 1) * 2;
        mma16816(acc[i][nt], ah[i], bh[p][q], bh[p][q + 1]);
        mma16816(acc[i][nt], ah[i], bl[p][q], bl[p][q + 1]);
        mma16816(acc[i][nt], al[i], bh[p][q], bh[p][q + 1]);
      }
    }
  }
}

// ---------------------------------------------------------------------------
// Persistent fused kernel: recurrence (CTAs 0..63) + out-GEMM workers (rest).
// ---------------------------------------------------------------------------
__global__ __launch_bounds__(256, 1) void fused_kernel(
    const int* __restrict__ tgt, const float* __restrict__ outb,
    float* __restrict__ out) {
  extern __shared__ __align__(1024) char smem[];
  __shared__ unsigned sidx;
  uint32_t su = (uint32_t)__cvta_generic_to_shared(smem);
  int tid = threadIdx.x;
  int lane = tid & 31, wid = tid >> 5;
  int wm = wid >> 1, wn = wid & 1;

  if (blockIdx.x < NC_STEP) {
    // ================= recurrence =================
    int mi = blockIdx.x >> 5, nblk = blockIdx.x & 31;
    int m0 = mi * 128, n0 = nblk * 64;

    // enc addend: resident for all steps
    {
      int r = tid >> 1, half = (tid & 1) * 32;
      const float* sc = d_encgateP + (size_t)(m0 + r) * G4 + n0 + half;
      uint32_t dc = su + ADD_ENC + (r * 64 + half) * 4;
#pragma unroll
      for (int q = 0; q < 8; ++q) cp16(dc + q * 16, sc + q * 4);
      cp_commit();
      cp_wait0();
    }
    __syncthreads();

    int em_r = tid >> 1, em_half = (tid & 1) * 32;
    int ep_m = tid >> 1, ep_k0 = (tid & 1) * 8;
    int ep_b = m0 + ep_m;
    int ep_kbase = nblk * 16 + ep_k0;
    const float* aE = (const float*)(smem + ADD_EMB) + ep_m * 64;
    const float* aC = (const float*)(smem + ADD_ENC) + ep_m * 64;
    float cpv[8] = {0.f, 0.f, 0.f, 0.f, 0.f, 0.f, 0.f, 0.f};

    for (int t = 0; t < Sn; ++t) {
      // emb addend for this step's tokens
      {
        int tok = tgt[(size_t)(m0 + em_r) * Sn + t];
        const float* se = d_embgateP + (size_t)tok * G4 + n0 + em_half;
        uint32_t de = su + ADD_EMB + (em_r * 64 + em_half) * 4;
#pragma unroll
        for (int q = 0; q < 8; ++q) cp16(de + q * 16, se + q * 4);
        cp_commit();
      }

      if (t > 0) {
        float acc[2][4][4] = {};
        const __nv_bfloat16* Ahi = d_hs_hi + ((size_t)(t - 1) * Bn + m0) * Hn;
        const __nv_bfloat16* Alo = d_hs_lo + ((size_t)(t - 1) * Bn + m0) * Hn;
        const __nv_bfloat16* Bhi = d_Whh_hi + (size_t)n0 * Hn;
        const __nv_bfloat16* Blo = d_Whh_lo + (size_t)n0 * Hn;
        LOADC_GEN(0, 0, Ahi, Alo, Bhi, Blo);
        LOADC_GEN(1, 1, Ahi, Alo, Bhi, Blo);
#pragma unroll 1
        for (int c = 0; c < 8; ++c) {
          if (c < 7) cp_wait1(); else cp_wait0();
          __syncthreads();
          compute_chunk(acc, su, c & 1, wm, wn, lane);
          __syncthreads();
          if (c + 2 < 8) LOADC_GEN(c + 2, c & 1, Ahi, Alo, Bhi, Blo);
        }
        // stage accum to Gs
        float* Gs = (float*)(smem + GS_OFF);
        int r0 = (lane >> 2), c0 = (lane & 3) * 2;
#pragma unroll
        for (int i = 0; i < 2; ++i) {
#pragma unroll
          for (int nt = 0; nt < 4; ++nt) {
            int row = wm * 32 + i * 16 + r0;
            int col = wn * 32 + nt * 8 + c0;
            Gs[row * GS_STRIDE + col]           = acc[i][nt][0];
            Gs[row * GS_STRIDE + col + 1]       = acc[i][nt][1];
            Gs[(row + 8) * GS_STRIDE + col]     = acc[i][nt][2];
            Gs[(row + 8) * GS_STRIDE + col + 1] = acc[i][nt][3];
          }
        }
      } else {
        cp_wait0();
      }
      __syncthreads();

      // ---- fused LSTM elementwise ----
      const float* Gs = (const float*)(smem + GS_OFF);
      __nv_bfloat16 hhi[8], hlo[8];
#pragma unroll
      for (int q = 0; q < 8; ++q) {
        int kk = ep_k0 + q;
        float gi = aE[kk]      + aC[kk];
        float gf = aE[16 + kk] + aC[16 + kk];
        float gg = aE[32 + kk] + aC[32 + kk];
        float go = aE[48 + kk] + aC[48 + kk];
        if (t > 0) {
          gi += Gs[ep_m * GS_STRIDE + kk];
          gf += Gs[ep_m * GS_STRIDE + 16 + kk];
          gg += Gs[ep_m * GS_STRIDE + 32 + kk];
          go += Gs[ep_m * GS_STRIDE + 48 + kk];
        }
        float iv = 1.f / (1.f + expf(-gi));
        float fv = 1.f / (1.f + expf(-gf));
        float gv = tanhf(gg);
        float ov = 1.f / (1.f + expf(-go));
        float cc = fv * cpv[q] + iv * gv;
        cpv[q] = cc;
        float hv = ov * tanhf(cc);
        __nv_bfloat16 hi = __float2bfloat16(hv);
        hhi[q] = hi;
        hlo[q] = __float2bfloat16(hv - __bfloat162float(hi));
      }
      {
        size_t hoff = ((size_t)t * Bn + ep_b) * Hn + ep_kbase;
        *(uint4*)(d_hs_hi + hoff) = *(const uint4*)hhi;
        *(uint4*)(d_hs_lo + hoff) = *(const uint4*)hlo;
      }

      // ---- global barrier over the 64 recurrence CTAs ----
      __threadfence();
      __syncthreads();
      if (tid == 0) {
        unsigned old = atomicAdd(&d_count, 1);
        if (old == NC_STEP - 1) {
          atomicExch(&d_count, 0);
          __threadfence();
          atomicAdd(&d_sense, 1);
        } else {
          while (ld_acq(&d_sense) < (unsigned)(t + 1)) { }
        }
      }
      __syncthreads();
    }
  }

  // ================= out-GEMM worker pool (all CTAs) =================
  for (;;) {
    __syncthreads();
    if (tid == 0) sidx = atomicAdd(&d_wq, 1);
    __syncthreads();
    unsigned idx = sidx;
    if (idx >= NOUT) break;
    int t = idx >> 5;
    int sub = idx & 31;
    int m0g = t * Bn + (sub >> 4) * 128;   // row in flattened hs
    int n0 = (sub & 15) * 64;

    if (tid == 0) {
      while (ld_acq(&d_sense) < (unsigned)(t + 1)) __nanosleep(128);
    }
    __syncthreads();

    const __nv_bfloat16* Ahi = d_hs_hi + (size_t)m0g * Hn;
    const __nv_bfloat16* Alo = d_hs_lo + (size_t)m0g * Hn;
    const __nv_bfloat16* Bhi = d_outW_hi + (size_t)n0 * Hn;
    const __nv_bfloat16* Blo = d_outW_lo + (size_t)n0 * Hn;

    float acc[2][4][4] = {};
    LOADC_GEN(0, 0, Ahi, Alo, Bhi, Blo);
    LOADC_GEN(1, 1, Ahi, Alo, Bhi, Blo);
#pragma unroll 1
    for (int c = 0; c < 8; ++c) {
      if (c < 7) cp_wait1(); else cp_wait0();
      __syncthreads();
      compute_chunk(acc, su, c & 1, wm, wn, lane);
      __syncthreads();
      if (c + 2 < 8) LOADC_GEN(c + 2, c & 1, Ahi, Alo, Bhi, Blo);
    }

    int r0 = lane >> 2, c0 = (lane & 3) * 2;
#pragma unroll
    for (int nt = 0; nt < 4; ++nt) {
      int v = n0 + wn * 32 + nt * 8 + c0;
      if (v >= Vn) continue;
      float b0 = outb[v], b1 = outb[v + 1];
#pragma unroll
      for (int i = 0; i < 2; ++i) {
        int mrow = m0g + wm * 32 + i * 16 + r0;
#pragma unroll
        for (int h = 0; h < 2; ++h) {
          int m = mrow + h * 8;
          int bb = m & 255;        // batch (B=256)
          float* dst = out + ((size_t)bb * Sn + t) * Vn + v;
          float2 o;
          o.x = acc[i][nt][h * 2 + 0] + b0;
          o.y = acc[i][nt][h * 2 + 1] + b1;
          *(float2*)dst = o;
        }
      }
    }
  }
}

extern "C" void kernel_launch(void* const* d_in, const int* in_sizes, int n_in,
                              void* d_out, int out_size) {
  const float* enc  = (const float*)d_in[0];
  const int*   tgt  = (const int*)  d_in[1];
  const float* emb  = (const float*)d_in[2];
  const float* Wih  = (const float*)d_in[3];
  const float* Whh  = (const float*)d_in[4];
  const float* bih  = (const float*)d_in[5];
  const float* bhh  = (const float*)d_in[6];
  // d_in[7..9] = attn_W, attn_b, v_w : dead (softmax over single source pos)
  const float* outW = (const float*)d_in[10];
  const float* outb = (const float*)d_in[11];
  float* out = (float*)d_out;

  cudaFuncSetAttribute(fused_kernel, cudaFuncAttributeMaxDynamicSharedMemorySize, FUSED_SMEM);

  reset_k<<<1, 1>>>();
  prep_whh<<<4096, 256>>>(Whh);
  prep_outw<<<2048, 256>>>(outW);
  encgate_kernel<<<dim3(4, 32), 256>>>(enc, Wih, bih, bhh);
  embgate_kernel<<<dim3(16, 32), 256>>>(emb, Wih);
  fused_kernel<<<NCTA, 256, FUSED_SMEM>>>(tgt, outb, out);
}

// round 6
// speedup vs baseline: 3.0819x; 1.7283x over previous
#include <cuda_runtime.h>
#include <cuda_bf16.h>
#include <cuda_fp16.h>
#include <math.h>
#include <stdint.h>

#define Bn 256
#define Sn 141
#define Vn 1000
#define En 256
#define Hn 512
#define G4 2048   // 4*H
#define VP 1024   // padded vocab

#define NC_STEP 128         // recurrence CTAs
#define NCTA    148         // persistent CTAs (1/SM)
#define NOUT    (Sn * 32)   // out tiles: per t, 2 m-tiles x 16 n-tiles

// ---------------- device scratch ----------------
__device__ float d_embgateP[(size_t)Vn * G4];     // [v][jp] fp32
__device__ float d_encgateP[(size_t)Bn * G4];     // [b][jp] fp32
__device__ __nv_bfloat16 d_Whh_hi[(size_t)G4 * Hn];   // [jp][k]
__device__ __nv_bfloat16 d_Whh_lo[(size_t)G4 * Hn];
__device__ __half d_outW_h[(size_t)VP * Hn];          // [v][k] fp16 hi
__device__ __half d_outW_l[(size_t)VP * Hn];          // [v][k] fp16 lo * 2^12
__device__ __nv_bfloat16 d_hs_hi[(size_t)Sn * Bn * Hn]; // [t][b][k]
__device__ __nv_bfloat16 d_hs_lo[(size_t)Sn * Bn * Hn];
__device__ __half d_hs_f16[(size_t)Sn * Bn * Hn];       // [t][b][k] fp16 (out GEMM A)

// sync state (reset each replay)
__device__ unsigned d_count;
__device__ unsigned d_sense;
__device__ unsigned d_wq;

__device__ __forceinline__ int jperm(int j) {
  return ((j & 511) >> 4) * 64 + (j >> 9) * 16 + (j & 15);
}

// ---------------- PTX helpers (plain sm_80+ only) ----------------
__device__ __forceinline__ void cp16(uint32_t dst, const void* src) {
  asm volatile("cp.async.cg.shared.global [%0], [%1], 16;" :: "r"(dst), "l"(src));
}
__device__ __forceinline__ void cp_commit() { asm volatile("cp.async.commit_group;"); }
__device__ __forceinline__ void cp_wait1() { asm volatile("cp.async.wait_group 1;" ::: "memory"); }
__device__ __forceinline__ void cp_wait0() { asm volatile("cp.async.wait_group 0;" ::: "memory"); }

__device__ __forceinline__ void ldm4(uint32_t& r0, uint32_t& r1, uint32_t& r2, uint32_t& r3,
                                     uint32_t addr) {
  asm volatile("ldmatrix.sync.aligned.m8n8.x4.shared.b16 {%0,%1,%2,%3}, [%4];"
               : "=r"(r0), "=r"(r1), "=r"(r2), "=r"(r3) : "r"(addr));
}
__device__ __forceinline__ void mma_bf16(float* d, const uint32_t* a, uint32_t b0, uint32_t b1) {
  asm volatile(
    "mma.sync.aligned.m16n8k16.row.col.f32.bf16.bf16.f32 "
    "{%0,%1,%2,%3}, {%4,%5,%6,%7}, {%8,%9}, {%0,%1,%2,%3};"
    : "+f"(d[0]), "+f"(d[1]), "+f"(d[2]), "+f"(d[3])
    : "r"(a[0]), "r"(a[1]), "r"(a[2]), "r"(a[3]), "r"(b0), "r"(b1));
}
__device__ __forceinline__ void mma_f16(float* d, const uint32_t* a, uint32_t b0, uint32_t b1) {
  asm volatile(
    "mma.sync.aligned.m16n8k16.row.col.f32.f16.f16.f32 "
    "{%0,%1,%2,%3}, {%4,%5,%6,%7}, {%8,%9}, {%0,%1,%2,%3};"
    : "+f"(d[0]), "+f"(d[1]), "+f"(d[2]), "+f"(d[3])
    : "r"(a[0]), "r"(a[1]), "r"(a[2]), "r"(a[3]), "r"(b0), "r"(b1));
}
__device__ __forceinline__ unsigned ld_acq(unsigned* p) {
  unsigned v;
  asm volatile("ld.acquire.gpu.u32 %0, [%1];" : "=r"(v) : "l"(p) : "memory");
  return v;
}

// ---------------- smem layout ----------------
// Recurrence buffers: A 64rows hi/lo + B 64rows hi/lo, 128B rows
#define STG_R    32768
#define RA_HI    0
#define RA_LO    8192
#define RB_HI    16384
#define RB_LO    24576
#define ADD_EMB  65536          // [64][64] f32 = 16K
#define ADD_ENC  81920          // [64][64] f32 = 16K
#define GS_OFF   98304          // [64][68] f32 = 17408
#define GS_STRIDE 68
#define FUSED_SMEM 115712
// Out buffers (reuse first 64K): A fp16 128 rows + B hi/lo 64 rows
#define STG_O    32768
#define OA_OFF   0
#define OB_HI    16384
#define OB_LO    24576

// ---------------------------------------------------------------------------
__global__ void reset_k() { d_count = 0; d_sense = 0; d_wq = 0; }

__global__ void prep_whh(const float* __restrict__ Whh) {
  int idx = blockIdx.x * 256 + threadIdx.x;       // 4H*H
  int j = idx >> 9, k = idx & 511;
  int jp = jperm(j);
  float x = Whh[idx];
  __nv_bfloat16 hi = __float2bfloat16(x);
  __nv_bfloat16 lo = __float2bfloat16(x - __bfloat162float(hi));
  d_Whh_hi[(size_t)jp * Hn + k] = hi;
  d_Whh_lo[(size_t)jp * Hn + k] = lo;
}

__global__ void prep_outw(const float* __restrict__ outW) {
  int idx = blockIdx.x * 256 + threadIdx.x;       // VP*Hn
  int v = idx >> 9, k = idx & 511;
  float x = (v < Vn) ? outW[(size_t)v * Hn + k] : 0.f;
  __half hi = __float2half_rn(x);
  __half lo = __float2half_rn((x - __half2float(hi)) * 4096.f);
  d_outW_h[idx] = hi;
  d_outW_l[idx] = lo;
}

// ---------------------------------------------------------------------------
// fp32 prep GEMMs (run once)
// ---------------------------------------------------------------------------
#define MMA16(As, Bs) do {                                                       \
    _Pragma("unroll")                                                            \
    for (int kk = 0; kk < 16; ++kk) {                                            \
      float4 a = *(const float4*)&As[kk][ty * 4];                                \
      float4 b = *(const float4*)&Bs[kk][tx * 4];                                \
      acc[0][0] += a.x*b.x; acc[0][1] += a.x*b.y; acc[0][2] += a.x*b.z; acc[0][3] += a.x*b.w; \
      acc[1][0] += a.y*b.x; acc[1][1] += a.y*b.y; acc[1][2] += a.y*b.z; acc[1][3] += a.y*b.w; \
      acc[2][0] += a.z*b.x; acc[2][1] += a.z*b.y; acc[2][2] += a.z*b.z; acc[2][3] += a.z*b.w; \
      acc[3][0] += a.w*b.x; acc[3][1] += a.w*b.y; acc[3][2] += a.w*b.z; acc[3][3] += a.w*b.w; \
    } } while (0)

__global__ __launch_bounds__(256) void encgate_kernel(
    const float* __restrict__ enc, const float* __restrict__ Wih,
    const float* __restrict__ bih, const float* __restrict__ bhh) {
  __shared__ float As[16][64];
  __shared__ float Bs[16][64];
  int tid = threadIdx.x;
  int m0 = blockIdx.x * 64, n0 = blockIdx.y * 64;
  int tx = tid & 15, ty = tid >> 4;
  int lr = tid >> 2, lq = tid & 3;
  float acc[4][4] = {};
  for (int kc = 0; kc < En; kc += 16) {
    float4 av = *(const float4*)(enc + (size_t)(m0 + lr) * En + kc + lq * 4);
    float4 bv = *(const float4*)(Wih + (size_t)(n0 + lr) * (2 * En) + En + kc + lq * 4);
    __syncthreads();
    As[lq*4+0][lr] = av.x; As[lq*4+1][lr] = av.y; As[lq*4+2][lr] = av.z; As[lq*4+3][lr] = av.w;
    Bs[lq*4+0][lr] = bv.x; Bs[lq*4+1][lr] = bv.y; Bs[lq*4+2][lr] = bv.z; Bs[lq*4+3][lr] = bv.w;
    __syncthreads();
    MMA16(As, Bs);
  }
#pragma unroll
  for (int ii = 0; ii < 4; ++ii) {
    int b = m0 + ty * 4 + ii;
#pragma unroll
    for (int jj = 0; jj < 4; ++jj) {
      int n = n0 + tx * 4 + jj;
      d_encgateP[(size_t)b * G4 + jperm(n)] = acc[ii][jj] + bih[n] + bhh[n];
    }
  }
}

__global__ __launch_bounds__(256) void embgate_kernel(
    const float* __restrict__ emb, const float* __restrict__ Wih) {
  __shared__ float As[16][64];
  __shared__ float Bs[16][64];
  int tid = threadIdx.x;
  int m0 = blockIdx.x * 64, n0 = blockIdx.y * 64;
  int tx = tid & 15, ty = tid >> 4;
  int lr = tid >> 2, lq = tid & 3;
  float acc[4][4] = {};
  for (int kc = 0; kc < En; kc += 16) {
    float4 av = make_float4(0.f, 0.f, 0.f, 0.f);
    if (m0 + lr < Vn)
      av = *(const float4*)(emb + (size_t)(m0 + lr) * En + kc + lq * 4);
    float4 bv = *(const float4*)(Wih + (size_t)(n0 + lr) * (2 * En) + kc + lq * 4);
    __syncthreads();
    As[lq*4+0][lr] = av.x; As[lq*4+1][lr] = av.y; As[lq*4+2][lr] = av.z; As[lq*4+3][lr] = av.w;
    Bs[lq*4+0][lr] = bv.x; Bs[lq*4+1][lr] = bv.y; Bs[lq*4+2][lr] = bv.z; Bs[lq*4+3][lr] = bv.w;
    __syncthreads();
    MMA16(As, Bs);
  }
#pragma unroll
  for (int ii = 0; ii < 4; ++ii) {
    int v = m0 + ty * 4 + ii;
    if (v >= Vn) continue;
#pragma unroll
    for (int jj = 0; jj < 4; ++jj) {
      int n = n0 + tx * 4 + jj;
      d_embgateP[(size_t)v * G4 + jperm(n)] = acc[ii][jj];
    }
  }
}

// ============================================================================
// Recurrence tile machinery: CTA tile 64x64, warp tile 16x32 (8 warps).
// ============================================================================
#define LOADC_R(c, buf, AhiP, AloP, BhiP, BloP)  do {                            \
    int kc = (c) * 64;                                                           \
    uint32_t st = su + (buf) * STG_R;                                            \
    int row = tid >> 2;                                                          \
    int sg0 = (tid & 3) * 2;                                                     \
    uint32_t sw = (uint32_t)(row & 7) * 16;                                      \
    _Pragma("unroll")                                                            \
    for (int q = 0; q < 2; ++q) {                                                \
      int sg = sg0 + q;                                                          \
      uint32_t so = (uint32_t)row * 128 + (((uint32_t)(sg * 16)) ^ sw);          \
      cp16(st + RA_HI + so, (AhiP) + (size_t)row * Hn + kc + sg * 8);            \
      cp16(st + RA_LO + so, (AloP) + (size_t)row * Hn + kc + sg * 8);            \
      cp16(st + RB_HI + so, (BhiP) + (size_t)row * Hn + kc + sg * 8);            \
      cp16(st + RB_LO + so, (BloP) + (size_t)row * Hn + kc + sg * 8);            \
    }                                                                            \
    cp_commit();                                                                 \
  } while (0)

__device__ __forceinline__ void compute_chunk_r(
    float acc[4][4], uint32_t su, int buf, int wm, int wn, int lane) {
  uint32_t base = su + buf * STG_R;
  int lr = lane & 7;
  int sel = lane >> 3;
  int a_roff = (sel & 1) * 8;
  int a_koff = (sel & 2) * 8;
  int b_koff = (sel & 1) * 16;
  int b_roff = (sel & 2) * 4;
  uint32_t swm = (uint32_t)(lr * 16);

#pragma unroll
  for (int ks = 0; ks < 4; ++ks) {
    int kb = ks * 32;
    uint32_t ah[4], al[4], bh[2][4], bl[2][4];
    {
      int row = wm * 16 + lr + a_roff;
      uint32_t off = (uint32_t)row * 128 + (((uint32_t)(kb + a_koff)) ^ swm);
      ldm4(ah[0], ah[1], ah[2], ah[3], base + RA_HI + off);
      ldm4(al[0], al[1], al[2], al[3], base + RA_LO + off);
    }
#pragma unroll
    for (int p = 0; p < 2; ++p) {
      int row = wn * 32 + p * 16 + lr + b_roff;
      uint32_t off = (uint32_t)row * 128 + (((uint32_t)(kb + b_koff)) ^ swm);
      ldm4(bh[p][0], bh[p][1], bh[p][2], bh[p][3], base + RB_HI + off);
      ldm4(bl[p][0], bl[p][1], bl[p][2], bl[p][3], base + RB_LO + off);
    }
#pragma unroll
    for (int nt = 0; nt < 4; ++nt) {
      int p = nt >> 1, q = (nt & 1) * 2;
      mma_bf16(acc[nt], ah, bh[p][q], bh[p][q + 1]);
      mma_bf16(acc[nt], ah, bl[p][q], bl[p][q + 1]);
      mma_bf16(acc[nt], al, bh[p][q], bh[p][q + 1]);
    }
  }
}

// ============================================================================
// Out tile machinery: CTA tile 128x64, warp tile 32x32, A fp16, B fp16 hi/lo.
// ============================================================================
#define LOADC_O(c, buf, AP, BhP, BlP)  do {                                      \
    int kc = (c) * 64;                                                           \
    uint32_t st = su + (buf) * STG_O;                                            \
    {                                                                            \
      int rowA = tid >> 1;                                                       \
      int sg0 = (tid & 1) * 4;                                                   \
      uint32_t swA = (uint32_t)(rowA & 7) * 16;                                  \
      _Pragma("unroll")                                                          \
      for (int q = 0; q < 4; ++q) {                                              \
        int sg = sg0 + q;                                                        \
        uint32_t so = (uint32_t)rowA * 128 + (((uint32_t)(sg * 16)) ^ swA);      \
        cp16(st + OA_OFF + so, (AP) + (size_t)rowA * Hn + kc + sg * 8);          \
      }                                                                          \
    }                                                                            \
    {                                                                            \
      int rB = tid >> 2;                                                         \
      int sg0 = (tid & 3) * 2;                                                   \
      uint32_t swB = (uint32_t)(rB & 7) * 16;                                    \
      _Pragma("unroll")                                                          \
      for (int q = 0; q < 2; ++q) {                                              \
        int sg = sg0 + q;                                                        \
        uint32_t so = (uint32_t)rB * 128 + (((uint32_t)(sg * 16)) ^ swB);        \
        cp16(st + OB_HI + so, (BhP) + (size_t)rB * Hn + kc + sg * 8);            \
        cp16(st + OB_LO + so, (BlP) + (size_t)rB * Hn + kc + sg * 8);            \
      }                                                                          \
    }                                                                            \
    cp_commit();                                                                 \
  } while (0)

__device__ __forceinline__ void compute_chunk_o(
    float accH[2][4][4], float accL[2][4][4], uint32_t su, int buf,
    int wm, int wn, int lane) {
  uint32_t base = su + buf * STG_O;
  int lr = lane & 7;
  int sel = lane >> 3;
  int a_roff = (sel & 1) * 8;
  int a_koff = (sel & 2) * 8;
  int b_koff = (sel & 1) * 16;
  int b_roff = (sel & 2) * 4;
  uint32_t swm = (uint32_t)(lr * 16);

#pragma unroll
  for (int ks = 0; ks < 4; ++ks) {
    int kb = ks * 32;
    uint32_t a[2][4], bh[2][4], bl[2][4];
#pragma unroll
    for (int i = 0; i < 2; ++i) {
      int row = wm * 32 + i * 16 + lr + a_roff;
      uint32_t off = (uint32_t)row * 128 + (((uint32_t)(kb + a_koff)) ^ swm);
      ldm4(a[i][0], a[i][1], a[i][2], a[i][3], base + OA_OFF + off);
    }
#pragma unroll
    for (int p = 0; p < 2; ++p) {
      int row = wn * 32 + p * 16 + lr + b_roff;
      uint32_t off = (uint32_t)row * 128 + (((uint32_t)(kb + b_koff)) ^ swm);
      ldm4(bh[p][0], bh[p][1], bh[p][2], bh[p][3], base + OB_HI + off);
      ldm4(bl[p][0], bl[p][1], bl[p][2], bl[p][3], base + OB_LO + off);
    }
#pragma unroll
    for (int i = 0; i < 2; ++i) {
#pragma unroll
      for (int nt = 0; nt < 4; ++nt) {
        int p = nt >> 1, q = (nt & 1) * 2;
        mma_f16(accH[i][nt], a[i], bh[p][q], bh[p][q + 1]);
        mma_f16(accL[i][nt], a[i], bl[p][q], bl[p][q + 1]);
      }
    }
  }
}

// ---------------------------------------------------------------------------
// Persistent fused kernel.
// ---------------------------------------------------------------------------
__global__ __launch_bounds__(256, 1) void fused_kernel(
    const int* __restrict__ tgt, const float* __restrict__ outb,
    float* __restrict__ out) {
  extern __shared__ __align__(1024) char smem[];
  __shared__ unsigned sidx;
  uint32_t su = (uint32_t)__cvta_generic_to_shared(smem);
  int tid = threadIdx.x;
  int lane = tid & 31, wid = tid >> 5;

  if (blockIdx.x < NC_STEP) {
    // ================= recurrence: CTA tile 64 b-rows x 64 jp-cols =========
    int wm = wid >> 1, wn = wid & 1;
    int mi = blockIdx.x >> 5, nblk = blockIdx.x & 31;
    int m0 = mi * 64, n0 = nblk * 64;

    // enc addend resident
    {
      int r = tid >> 2, sg0 = (tid & 3) * 4;
      const float* sc = d_encgateP + (size_t)(m0 + r) * G4 + n0;
      uint32_t dc = su + ADD_ENC + r * 256;
#pragma unroll
      for (int q = 0; q < 4; ++q)
        cp16(dc + (sg0 + q) * 16, sc + (sg0 + q) * 4);
      cp_commit();
      cp_wait0();
    }
    __syncthreads();

    int em_r = tid >> 2, em_sg = (tid & 3) * 4;
    int ep_m = tid >> 2, ep_k0 = (tid & 3) * 4;
    int ep_b = m0 + ep_m;
    int ep_kbase = nblk * 16 + ep_k0;
    const float* aE = (const float*)(smem + ADD_EMB) + ep_m * 64;
    const float* aC = (const float*)(smem + ADD_ENC) + ep_m * 64;
    float cpv[4] = {0.f, 0.f, 0.f, 0.f};

    for (int t = 0; t < Sn; ++t) {
      // emb addend for this step
      {
        int tok = tgt[(size_t)(m0 + em_r) * Sn + t];
        const float* se = d_embgateP + (size_t)tok * G4 + n0;
        uint32_t de = su + ADD_EMB + em_r * 256;
#pragma unroll
        for (int q = 0; q < 4; ++q)
          cp16(de + (em_sg + q) * 16, se + (em_sg + q) * 4);
        cp_commit();
      }

      if (t > 0) {
        float acc[4][4] = {};
        const __nv_bfloat16* Ahi = d_hs_hi + ((size_t)(t - 1) * Bn + m0) * Hn;
        const __nv_bfloat16* Alo = d_hs_lo + ((size_t)(t - 1) * Bn + m0) * Hn;
        const __nv_bfloat16* Bhi = d_Whh_hi + (size_t)n0 * Hn;
        const __nv_bfloat16* Blo = d_Whh_lo + (size_t)n0 * Hn;
        LOADC_R(0, 0, Ahi, Alo, Bhi, Blo);
        LOADC_R(1, 1, Ahi, Alo, Bhi, Blo);
#pragma unroll 1
        for (int c = 0; c < 8; ++c) {
          if (c < 7) cp_wait1(); else cp_wait0();
          __syncthreads();
          compute_chunk_r(acc, su, c & 1, wm, wn, lane);
          __syncthreads();
          if (c + 2 < 8) LOADC_R(c + 2, c & 1, Ahi, Alo, Bhi, Blo);
        }
        // stage to Gs
        float* Gs = (float*)(smem + GS_OFF);
        int r0 = (lane >> 2), c0 = (lane & 3) * 2;
#pragma unroll
        for (int nt = 0; nt < 4; ++nt) {
          int row = wm * 16 + r0;
          int col = wn * 32 + nt * 8 + c0;
          Gs[row * GS_STRIDE + col]           = acc[nt][0];
          Gs[row * GS_STRIDE + col + 1]       = acc[nt][1];
          Gs[(row + 8) * GS_STRIDE + col]     = acc[nt][2];
          Gs[(row + 8) * GS_STRIDE + col + 1] = acc[nt][3];
        }
      } else {
        cp_wait0();
      }
      __syncthreads();

      // ---- fused LSTM elementwise: 4 cells/thread ----
      const float* Gs = (const float*)(smem + GS_OFF);
      __nv_bfloat16 hhi[4], hlo[4];
      __half hf[4];
#pragma unroll
      for (int q = 0; q < 4; ++q) {
        int kk = ep_k0 + q;
        float gi = aE[kk]      + aC[kk];
        float gf = aE[16 + kk] + aC[16 + kk];
        float gg = aE[32 + kk] + aC[32 + kk];
        float go = aE[48 + kk] + aC[48 + kk];
        if (t > 0) {
          gi += Gs[ep_m * GS_STRIDE + kk];
          gf += Gs[ep_m * GS_STRIDE + 16 + kk];
          gg += Gs[ep_m * GS_STRIDE + 32 + kk];
          go += Gs[ep_m * GS_STRIDE + 48 + kk];
        }
        float iv = 1.f / (1.f + expf(-gi));
        float fv = 1.f / (1.f + expf(-gf));
        float gv = tanhf(gg);
        float ov = 1.f / (1.f + expf(-go));
        float cc = fv * cpv[q] + iv * gv;
        cpv[q] = cc;
        float hv = ov * tanhf(cc);
        __nv_bfloat16 hi = __float2bfloat16(hv);
        hhi[q] = hi;
        hlo[q] = __float2bfloat16(hv - __bfloat162float(hi));
        hf[q] = __float2half_rn(hv);
      }
      {
        size_t hoff = ((size_t)t * Bn + ep_b) * Hn + ep_kbase;
        *(uint2*)(d_hs_hi + hoff)  = *(const uint2*)hhi;
        *(uint2*)(d_hs_lo + hoff)  = *(const uint2*)hlo;
        *(uint2*)(d_hs_f16 + hoff) = *(const uint2*)hf;
      }

      // ---- global barrier over recurrence CTAs ----
      __threadfence();
      __syncthreads();
      if (tid == 0) {
        unsigned old = atomicAdd(&d_count, 1);
        if (old == NC_STEP - 1) {
          atomicExch(&d_count, 0);
          __threadfence();
          atomicAdd(&d_sense, 1);
        } else {
          while (ld_acq(&d_sense) < (unsigned)(t + 1)) { }
        }
      }
      __syncthreads();
    }
  }

  // ================= out-GEMM worker pool (all CTAs) =================
  {
    int wm = wid >> 1, wn = wid & 1;
    for (;;) {
      __syncthreads();
      if (tid == 0) sidx = atomicAdd(&d_wq, 1);
      __syncthreads();
      unsigned idx = sidx;
      if (idx >= NOUT) break;
      int t = idx >> 5;
      int sub = idx & 31;
      int m0g = t * Bn + (sub >> 4) * 128;
      int n0 = (sub & 15) * 64;

      if (tid == 0) {
        while (ld_acq(&d_sense) < (unsigned)(t + 1)) __nanosleep(128);
      }
      __syncthreads();

      const __half* A  = d_hs_f16 + (size_t)m0g * Hn;
      const __half* Bh = d_outW_h + (size_t)n0 * Hn;
      const __half* Bl = d_outW_l + (size_t)n0 * Hn;

      float accH[2][4][4] = {};
      float accL[2][4][4] = {};
      LOADC_O(0, 0, A, Bh, Bl);
      LOADC_O(1, 1, A, Bh, Bl);
#pragma unroll 1
      for (int c = 0; c < 8; ++c) {
        if (c < 7) cp_wait1(); else cp_wait0();
        __syncthreads();
        compute_chunk_o(accH, accL, su, c & 1, wm, wn, lane);
        __syncthreads();
        if (c + 2 < 8) LOADC_O(c + 2, c & 1, A, Bh, Bl);
      }

      int r0 = lane >> 2, c0 = (lane & 3) * 2;
#pragma unroll
      for (int nt = 0; nt < 4; ++nt) {
        int v = n0 + wn * 32 + nt * 8 + c0;
        if (v >= Vn) continue;
        float b0 = outb[v], b1 = outb[v + 1];
#pragma unroll
        for (int i = 0; i < 2; ++i) {
          int mrow = m0g + wm * 32 + i * 16 + r0;
#pragma unroll
          for (int h = 0; h < 2; ++h) {
            int m = mrow + h * 8;
            int bb = m & 255;
            float* dst = out + ((size_t)bb * Sn + t) * Vn + v;
            float2 o;
            o.x = accH[i][nt][h * 2 + 0] + accL[i][nt][h * 2 + 0] * (1.f / 4096.f) + b0;
            o.y = accH[i][nt][h * 2 + 1] + accL[i][nt][h * 2 + 1] * (1.f / 4096.f) + b1;
            *(float2*)dst = o;
          }
        }
      }
    }
  }
}

extern "C" void kernel_launch(void* const* d_in, const int* in_sizes, int n_in,
                              void* d_out, int out_size) {
  const float* enc  = (const float*)d_in[0];
  const int*   tgt  = (const int*)  d_in[1];
  const float* emb  = (const float*)d_in[2];
  const float* Wih  = (const float*)d_in[3];
  const float* Whh  = (const float*)d_in[4];
  const float* bih  = (const float*)d_in[5];
  const float* bhh  = (const float*)d_in[6];
  // d_in[7..9] = attn_W, attn_b, v_w : dead (softmax over single source pos)
  const float* outW = (const float*)d_in[10];
  const float* outb = (const float*)d_in[11];
  float* out = (float*)d_out;

  cudaFuncSetAttribute(fused_kernel, cudaFuncAttributeMaxDynamicSharedMemorySize, FUSED_SMEM);

  reset_k<<<1, 1>>>();
  prep_whh<<<4096, 256>>>(Whh);
  prep_outw<<<2048, 256>>>(outW);
  encgate_kernel<<<dim3(4, 32), 256>>>(enc, Wih, bih, bhh);
  embgate_kernel<<<dim3(16, 32), 256>>>(emb, Wih);
  fused_kernel<<<NCTA, 256, FUSED_SMEM>>>(tgt, outb, out);
}

// round 7
// speedup vs baseline: 3.5073x; 1.1380x over previous
#include <cuda_runtime.h>
#include <cuda_bf16.h>
#include <cuda_fp16.h>
#include <math.h>
#include <stdint.h>

#define Bn 256
#define Sn 141
#define Vn 1000
#define En 256
#define Hn 512
#define G4 2048   // 4*H
#define VP 1024   // padded vocab

#define NC_STEP 128         // recurrence CTAs (4 groups of 32)
#define NCTA    148         // persistent CTAs (1/SM)
#define NOUT    (Sn * 32)   // out tiles: per t, 2 m-tiles x 16 n-tiles

// ---------------- device scratch ----------------
__device__ float d_embgateP[(size_t)Vn * G4];     // [v][jp] fp32
__device__ float d_encgateP[(size_t)Bn * G4];     // [b][jp] fp32
__device__ __half d_Whh_h[(size_t)G4 * Hn];       // [jp][k] fp16 hi
__device__ __half d_Whh_l[(size_t)G4 * Hn];       // [jp][k] fp16 lo * 2^12
__device__ __half d_outW_h[(size_t)VP * Hn];      // [v][k] fp16 hi
__device__ __half d_outW_l[(size_t)VP * Hn];      // [v][k] fp16 lo * 2^12
__device__ __half d_hs_f16[(size_t)Sn * Bn * Hn]; // [t][b][k] fp16 (A everywhere)

// sync state (reset by prep kernel each replay); 128B-spaced counters
__device__ unsigned d_countg[4 * 32];
__device__ unsigned d_senseg[4 * 32];
__device__ unsigned d_wq;

__device__ __forceinline__ int jperm(int j) {
  return ((j & 511) >> 4) * 64 + (j >> 9) * 16 + (j & 15);
}

// ---------------- PTX helpers (plain sm_80+ only) ----------------
__device__ __forceinline__ void cp16(uint32_t dst, const void* src) {
  asm volatile("cp.async.cg.shared.global [%0], [%1], 16;" :: "r"(dst), "l"(src));
}
__device__ __forceinline__ void cp_commit() { asm volatile("cp.async.commit_group;"); }
__device__ __forceinline__ void cp_wait1() { asm volatile("cp.async.wait_group 1;" ::: "memory"); }
__device__ __forceinline__ void cp_wait0() { asm volatile("cp.async.wait_group 0;" ::: "memory"); }

__device__ __forceinline__ void ldm4(uint32_t& r0, uint32_t& r1, uint32_t& r2, uint32_t& r3,
                                     uint32_t addr) {
  asm volatile("ldmatrix.sync.aligned.m8n8.x4.shared.b16 {%0,%1,%2,%3}, [%4];"
               : "=r"(r0), "=r"(r1), "=r"(r2), "=r"(r3) : "r"(addr));
}
__device__ __forceinline__ void mma_f16(float* d, const uint32_t* a, uint32_t b0, uint32_t b1) {
  asm volatile(
    "mma.sync.aligned.m16n8k16.row.col.f32.f16.f16.f32 "
    "{%0,%1,%2,%3}, {%4,%5,%6,%7}, {%8,%9}, {%0,%1,%2,%3};"
    : "+f"(d[0]), "+f"(d[1]), "+f"(d[2]), "+f"(d[3])
    : "r"(a[0]), "r"(a[1]), "r"(a[2]), "r"(a[3]), "r"(b0), "r"(b1));
}
__device__ __forceinline__ unsigned ld_acq(unsigned* p) {
  unsigned v;
  asm volatile("ld.acquire.gpu.u32 %0, [%1];" : "=r"(v) : "l"(p) : "memory");
  return v;
}

// ---------------- smem layout ----------------
// Recurrence: A fp16 64 rows + B hi/lo 64 rows, 128B rows. 24K per buffer.
#define STG_R    24576
#define RA_OFF   0
#define RB_HI    8192
#define RB_LO    16384
#define ADD_EMB  49152          // [64][64] f32 = 16K
#define ADD_ENC  65536          // [64][64] f32 = 16K
#define GS_OFF   81920          // [64][68] f32 = 17408
#define GS_STRIDE 68
#define FUSED_SMEM 99328
// Out: A fp16 128 rows + B hi/lo 64 rows. 32K per buffer.
#define STG_O    32768
#define OA_OFF   0
#define OB_HI    16384
#define OB_LO    24576

// ---------------------------------------------------------------------------
// Merged prep kernel. Block ranges:
//   [0,512)      embgate tiles (16 m x 32 n)
//   [512,640)    encgate tiles (4 m x 32 n)
//   [640,1664)   Whh convert   (1024 blocks x 256 thr x 1 float4)
//   [1664,2176)  outW convert  (512 blocks)
//   2176         flag reset
// ---------------------------------------------------------------------------
#define MMA16(As, Bs) do {                                                       \
    _Pragma("unroll")                                                            \
    for (int kk = 0; kk < 16; ++kk) {                                            \
      float4 a = *(const float4*)&As[kk][ty * 4];                                \
      float4 b = *(const float4*)&Bs[kk][tx * 4];                                \
      acc[0][0] += a.x*b.x; acc[0][1] += a.x*b.y; acc[0][2] += a.x*b.z; acc[0][3] += a.x*b.w; \
      acc[1][0] += a.y*b.x; acc[1][1] += a.y*b.y; acc[1][2] += a.y*b.z; acc[1][3] += a.y*b.w; \
      acc[2][0] += a.z*b.x; acc[2][1] += a.z*b.y; acc[2][2] += a.z*b.z; acc[2][3] += a.z*b.w; \
      acc[3][0] += a.w*b.x; acc[3][1] += a.w*b.y; acc[3][2] += a.w*b.z; acc[3][3] += a.w*b.w; \
    } } while (0)

__global__ __launch_bounds__(256) void prep_all(
    const float* __restrict__ enc, const float* __restrict__ emb,
    const float* __restrict__ Wih, const float* __restrict__ Whh,
    const float* __restrict__ bih, const float* __restrict__ bhh,
    const float* __restrict__ outW) {
  __shared__ float As[16][64];
  __shared__ float Bs[16][64];
  int bid = blockIdx.x;
  int tid = threadIdx.x;

  if (bid < 512 || (bid >= 512 && bid < 640)) {
    // ---- GEMM tiles ----
    bool is_emb = bid < 512;
    int m0, n0;
    if (is_emb) { m0 = (bid & 15) * 64; n0 = (bid >> 4) * 64; }
    else        { int b2 = bid - 512; m0 = (b2 & 3) * 64; n0 = (b2 >> 2) * 64; }
    int tx = tid & 15, ty = tid >> 4;
    int lr = tid >> 2, lq = tid & 3;
    float acc[4][4] = {};
    for (int kc = 0; kc < En; kc += 16) {
      float4 av = make_float4(0.f, 0.f, 0.f, 0.f);
      float4 bv;
      if (is_emb) {
        if (m0 + lr < Vn)
          av = *(const float4*)(emb + (size_t)(m0 + lr) * En + kc + lq * 4);
        bv = *(const float4*)(Wih + (size_t)(n0 + lr) * (2 * En) + kc + lq * 4);
      } else {
        av = *(const float4*)(enc + (size_t)(m0 + lr) * En + kc + lq * 4);
        bv = *(const float4*)(Wih + (size_t)(n0 + lr) * (2 * En) + En + kc + lq * 4);
      }
      __syncthreads();
      As[lq*4+0][lr] = av.x; As[lq*4+1][lr] = av.y; As[lq*4+2][lr] = av.z; As[lq*4+3][lr] = av.w;
      Bs[lq*4+0][lr] = bv.x; Bs[lq*4+1][lr] = bv.y; Bs[lq*4+2][lr] = bv.z; Bs[lq*4+3][lr] = bv.w;
      __syncthreads();
      MMA16(As, Bs);
    }
#pragma unroll
    for (int ii = 0; ii < 4; ++ii) {
      int m = m0 + ty * 4 + ii;
      if (is_emb && m >= Vn) continue;
#pragma unroll
      for (int jj = 0; jj < 4; ++jj) {
        int n = n0 + tx * 4 + jj;
        if (is_emb)
          d_embgateP[(size_t)m * G4 + jperm(n)] = acc[ii][jj];
        else
          d_encgateP[(size_t)m * G4 + jperm(n)] = acc[ii][jj] + bih[n] + bhh[n];
      }
    }
  } else if (bid < 1664) {
    // ---- Whh fp32 -> fp16 hi/lo, row-permute [jp][k] ----
    int i = (bid - 640) * 256 + tid;                // float4 index over 4H*H/4
    int e0 = i * 4;
    int j = e0 >> 9, k0 = e0 & 511;
    int jp = jperm(j);
    float4 x = *(const float4*)(Whh + e0);
    __half h[4], l[4];
    float xs[4] = {x.x, x.y, x.z, x.w};
#pragma unroll
    for (int q = 0; q < 4; ++q) {
      h[q] = __float2half_rn(xs[q]);
      l[q] = __float2half_rn((xs[q] - __half2float(h[q])) * 4096.f);
    }
    *(uint2*)(d_Whh_h + (size_t)jp * Hn + k0) = *(const uint2*)h;
    *(uint2*)(d_Whh_l + (size_t)jp * Hn + k0) = *(const uint2*)l;
  } else if (bid < 2176) {
    // ---- outW fp32 -> fp16 hi/lo, zero-padded ----
    int i = (bid - 1664) * 256 + tid;               // float4 over VP*Hn/4
    int e0 = i * 4;
    int v = e0 >> 9, k0 = e0 & 511;
    __half h[4], l[4];
    if (v < Vn) {
      float4 x = *(const float4*)(outW + (size_t)v * Hn + k0);
      float xs[4] = {x.x, x.y, x.z, x.w};
#pragma unroll
      for (int q = 0; q < 4; ++q) {
        h[q] = __float2half_rn(xs[q]);
        l[q] = __float2half_rn((xs[q] - __half2float(h[q])) * 4096.f);
      }
    } else {
#pragma unroll
      for (int q = 0; q < 4; ++q) { h[q] = __float2half_rn(0.f); l[q] = h[q]; }
    }
    *(uint2*)(d_outW_h + e0) = *(const uint2*)h;
    *(uint2*)(d_outW_l + e0) = *(const uint2*)l;
  } else {
    if (tid < 128) d_countg[tid] = 0;
    else if (tid < 256) d_senseg[tid - 128] = 0;
    if (tid == 0) d_wq = 0;
  }
}

// ============================================================================
// Recurrence tile machinery: CTA tile 64x64, warp tile 16x32 (8 warps).
// A = h fp16 (1 op), B = Whh fp16 hi + lo*2^12 (2 chains).
// ============================================================================
#define LOADC_R(c, buf, AP, BhP, BlP)  do {                                      \
    int kc = (c) * 64;                                                           \
    uint32_t st = su + (buf) * STG_R;                                            \
    int row = tid >> 2;                                                          \
    int sg0 = (tid & 3) * 2;                                                     \
    uint32_t sw = (uint32_t)(row & 7) * 16;                                      \
    _Pragma("unroll")                                                            \
    for (int q = 0; q < 2; ++q) {                                                \
      int sg = sg0 + q;                                                          \
      uint32_t so = (uint32_t)row * 128 + (((uint32_t)(sg * 16)) ^ sw);          \
      cp16(st + RA_OFF + so, (AP) + (size_t)row * Hn + kc + sg * 8);             \
      cp16(st + RB_HI + so, (BhP) + (size_t)row * Hn + kc + sg * 8);             \
      cp16(st + RB_LO + so, (BlP) + (size_t)row * Hn + kc + sg * 8);             \
    }                                                                            \
    cp_commit();                                                                 \
  } while (0)

__device__ __forceinline__ void compute_chunk_r(
    float accH[4][4], float accL[4][4], uint32_t su, int buf,
    int wm, int wn, int lane) {
  uint32_t base = su + buf * STG_R;
  int lr = lane & 7;
  int sel = lane >> 3;
  int a_roff = (sel & 1) * 8;
  int a_koff = (sel & 2) * 8;
  int b_koff = (sel & 1) * 16;
  int b_roff = (sel & 2) * 4;
  uint32_t swm = (uint32_t)(lr * 16);

#pragma unroll
  for (int ks = 0; ks < 4; ++ks) {
    int kb = ks * 32;
    uint32_t a[4], bh[2][4], bl[2][4];
    {
      int row = wm * 16 + lr + a_roff;
      uint32_t off = (uint32_t)row * 128 + (((uint32_t)(kb + a_koff)) ^ swm);
      ldm4(a[0], a[1], a[2], a[3], base + RA_OFF + off);
    }
#pragma unroll
    for (int p = 0; p < 2; ++p) {
      int row = wn * 32 + p * 16 + lr + b_roff;
      uint32_t off = (uint32_t)row * 128 + (((uint32_t)(kb + b_koff)) ^ swm);
      ldm4(bh[p][0], bh[p][1], bh[p][2], bh[p][3], base + RB_HI + off);
      ldm4(bl[p][0], bl[p][1], bl[p][2], bl[p][3], base + RB_LO + off);
    }
#pragma unroll
    for (int nt = 0; nt < 4; ++nt) {
      int p = nt >> 1, q = (nt & 1) * 2;
      mma_f16(accH[nt], a, bh[p][q], bh[p][q + 1]);
      mma_f16(accL[nt], a, bl[p][q], bl[p][q + 1]);
    }
  }
}

// ============================================================================
// Out tile machinery: CTA tile 128x64, warp tile 32x32.
// ============================================================================
#define LOADC_O(c, buf, AP, BhP, BlP)  do {                                      \
    int kc = (c) * 64;                                                           \
    uint32_t st = su + (buf) * STG_O;                                            \
    {                                                                            \
      int rowA = tid >> 1;                                                       \
      int sg0 = (tid & 1) * 4;                                                   \
      uint32_t swA = (uint32_t)(rowA & 7) * 16;                                  \
      _Pragma("unroll")                                                          \
      for (int q = 0; q < 4; ++q) {                                              \
        int sg = sg0 + q;                                                        \
        uint32_t so = (uint32_t)rowA * 128 + (((uint32_t)(sg * 16)) ^ swA);      \
        cp16(st + OA_OFF + so, (AP) + (size_t)rowA * Hn + kc + sg * 8);          \
      }                                                                          \
    }                                                                            \
    {                                                                            \
      int rB = tid >> 2;                                                         \
      int sg0 = (tid & 3) * 2;                                                   \
      uint32_t swB = (uint32_t)(rB & 7) * 16;                                    \
      _Pragma("unroll")                                                          \
      for (int q = 0; q < 2; ++q) {                                              \
        int sg = sg0 + q;                                                        \
        uint32_t so = (uint32_t)rB * 128 + (((uint32_t)(sg * 16)) ^ swB);        \
        cp16(st + OB_HI + so, (BhP) + (size_t)rB * Hn + kc + sg * 8);            \
        cp16(st + OB_LO + so, (BlP) + (size_t)rB * Hn + kc + sg * 8);            \
      }                                                                          \
    }                                                                            \
    cp_commit();                                                                 \
  } while (0)

__device__ __forceinline__ void compute_chunk_o(
    float accH[2][4][4], float accL[2][4][4], uint32_t su, int buf,
    int wm, int wn, int lane) {
  uint32_t base = su + buf * STG_O;
  int lr = lane & 7;
  int sel = lane >> 3;
  int a_roff = (sel & 1) * 8;
  int a_koff = (sel & 2) * 8;
  int b_koff = (sel & 1) * 16;
  int b_roff = (sel & 2) * 4;
  uint32_t swm = (uint32_t)(lr * 16);

#pragma unroll
  for (int ks = 0; ks < 4; ++ks) {
    int kb = ks * 32;
    uint32_t a[2][4], bh[2][4], bl[2][4];
#pragma unroll
    for (int i = 0; i < 2; ++i) {
      int row = wm * 32 + i * 16 + lr + a_roff;
      uint32_t off = (uint32_t)row * 128 + (((uint32_t)(kb + a_koff)) ^ swm);
      ldm4(a[i][0], a[i][1], a[i][2], a[i][3], base + OA_OFF + off);
    }
#pragma unroll
    for (int p = 0; p < 2; ++p) {
      int row = wn * 32 + p * 16 + lr + b_roff;
      uint32_t off = (uint32_t)row * 128 + (((uint32_t)(kb + b_koff)) ^ swm);
      ldm4(bh[p][0], bh[p][1], bh[p][2], bh[p][3], base + OB_HI + off);
      ldm4(bl[p][0], bl[p][1], bl[p][2], bl[p][3], base + OB_LO + off);
    }
#pragma unroll
    for (int i = 0; i < 2; ++i) {
#pragma unroll
      for (int nt = 0; nt < 4; ++nt) {
        int p = nt >> 1, q = (nt & 1) * 2;
        mma_f16(accH[i][nt], a[i], bh[p][q], bh[p][q + 1]);
        mma_f16(accL[i][nt], a[i], bl[p][q], bl[p][q + 1]);
      }
    }
  }
}

// ---------------------------------------------------------------------------
// Persistent fused kernel.
// ---------------------------------------------------------------------------
__global__ __launch_bounds__(256, 1) void fused_kernel(
    const int* __restrict__ tgt, const float* __restrict__ outb,
    float* __restrict__ out) {
  extern __shared__ __align__(1024) char smem[];
  __shared__ unsigned sidx;
  uint32_t su = (uint32_t)__cvta_generic_to_shared(smem);
  int tid = threadIdx.x;
  int lane = tid & 31, wid = tid >> 5;
  int wm = wid >> 1, wn = wid & 1;

  if (blockIdx.x < NC_STEP) {
    // ========== recurrence: CTA tile 64 b-rows x 64 jp-cols ==========
    int mi = blockIdx.x >> 5, nblk = blockIdx.x & 31;
    int m0 = mi * 64, n0 = nblk * 64;
    unsigned* myCount = &d_countg[mi * 32];
    unsigned* mySense = &d_senseg[mi * 32];

    // enc addend resident
    {
      int r = tid >> 2, sg0 = (tid & 3) * 4;
      const float* sc = d_encgateP + (size_t)(m0 + r) * G4 + n0;
      uint32_t dc = su + ADD_ENC + r * 256;
#pragma unroll
      for (int q = 0; q < 4; ++q)
        cp16(dc + (sg0 + q) * 16, sc + (sg0 + q) * 4);
      cp_commit();
      cp_wait0();
    }
    __syncthreads();

    int em_r = tid >> 2, em_sg = (tid & 3) * 4;
    int ep_m = tid >> 2, ep_k0 = (tid & 3) * 4;
    int ep_b = m0 + ep_m;
    int ep_kbase = nblk * 16 + ep_k0;
    const float* aE = (const float*)(smem + ADD_EMB) + ep_m * 64;
    const float* aC = (const float*)(smem + ADD_ENC) + ep_m * 64;
    float cpv[4] = {0.f, 0.f, 0.f, 0.f};

    for (int t = 0; t < Sn; ++t) {
      // emb addend for this step
      {
        int tok = tgt[(size_t)(m0 + em_r) * Sn + t];
        const float* se = d_embgateP + (size_t)tok * G4 + n0;
        uint32_t de = su + ADD_EMB + em_r * 256;
#pragma unroll
        for (int q = 0; q < 4; ++q)
          cp16(de + (em_sg + q) * 16, se + (em_sg + q) * 4);
        cp_commit();
      }

      if (t > 0) {
        float accH[4][4] = {};
        float accL[4][4] = {};
        const __half* A  = d_hs_f16 + ((size_t)(t - 1) * Bn + m0) * Hn;
        const __half* Bh = d_Whh_h + (size_t)n0 * Hn;
        const __half* Bl = d_Whh_l + (size_t)n0 * Hn;
        LOADC_R(0, 0, A, Bh, Bl);
        LOADC_R(1, 1, A, Bh, Bl);
#pragma unroll 1
        for (int c = 0; c < 8; ++c) {
          if (c < 7) cp_wait1(); else cp_wait0();
          __syncthreads();
          compute_chunk_r(accH, accL, su, c & 1, wm, wn, lane);
          __syncthreads();
          if (c + 2 < 8) LOADC_R(c + 2, c & 1, A, Bh, Bl);
        }
        // stage combined gates to Gs
        float* Gs = (float*)(smem + GS_OFF);
        int r0 = (lane >> 2), c0 = (lane & 3) * 2;
        const float kinv = 1.f / 4096.f;
#pragma unroll
        for (int nt = 0; nt < 4; ++nt) {
          int row = wm * 16 + r0;
          int col = wn * 32 + nt * 8 + c0;
          Gs[row * GS_STRIDE + col]           = accH[nt][0] + accL[nt][0] * kinv;
          Gs[row * GS_STRIDE + col + 1]       = accH[nt][1] + accL[nt][1] * kinv;
          Gs[(row + 8) * GS_STRIDE + col]     = accH[nt][2] + accL[nt][2] * kinv;
          Gs[(row + 8) * GS_STRIDE + col + 1] = accH[nt][3] + accL[nt][3] * kinv;
        }
      } else {
        cp_wait0();
      }
      __syncthreads();

      // ---- fused LSTM elementwise: 4 cells/thread ----
      const float* Gs = (const float*)(smem + GS_OFF);
      __half hf[4];
#pragma unroll
      for (int q = 0; q < 4; ++q) {
        int kk = ep_k0 + q;
        float gi = aE[kk]      + aC[kk];
        float gf = aE[16 + kk] + aC[16 + kk];
        float gg = aE[32 + kk] + aC[32 + kk];
        float go = aE[48 + kk] + aC[48 + kk];
        if (t > 0) {
          gi += Gs[ep_m * GS_STRIDE + kk];
          gf += Gs[ep_m * GS_STRIDE + 16 + kk];
          gg += Gs[ep_m * GS_STRIDE + 32 + kk];
          go += Gs[ep_m * GS_STRIDE + 48 + kk];
        }
        float iv = 1.f / (1.f + expf(-gi));
        float fv = 1.f / (1.f + expf(-gf));
        float gv = tanhf(gg);
        float ov = 1.f / (1.f + expf(-go));
        float cc = fv * cpv[q] + iv * gv;
        cpv[q] = cc;
        hf[q] = __float2half_rn(ov * tanhf(cc));
      }
      *(uint2*)(d_hs_f16 + ((size_t)t * Bn + ep_b) * Hn + ep_kbase) = *(const uint2*)hf;

      // ---- per-group (32-CTA) barrier ----
      __threadfence();
      __syncthreads();
      if (tid == 0) {
        unsigned old = atomicAdd(myCount, 1);
        if (old == 31) {
          atomicExch(myCount, 0);
          __threadfence();
          atomicAdd(mySense, 1);
        } else {
          while (ld_acq(mySense) < (unsigned)(t + 1)) { }
        }
      }
      __syncthreads();
    }
  }

  // ========== out-GEMM worker pool (all CTAs) ==========
  for (;;) {
    __syncthreads();
    if (tid == 0) sidx = atomicAdd(&d_wq, 1);
    __syncthreads();
    unsigned idx = sidx;
    if (idx >= NOUT) break;
    int t = idx >> 5;
    int sub = idx & 31;
    int mtile = sub >> 4;
    int m0g = t * Bn + mtile * 128;
    int n0 = (sub & 15) * 64;

    if (tid == 0) {
      unsigned* sA = &d_senseg[(mtile * 2) * 32];
      unsigned* sB = &d_senseg[(mtile * 2 + 1) * 32];
      while (ld_acq(sA) < (unsigned)(t + 1) || ld_acq(sB) < (unsigned)(t + 1))
        __nanosleep(128);
    }
    __syncthreads();

    const __half* A  = d_hs_f16 + (size_t)m0g * Hn;
    const __half* Bh = d_outW_h + (size_t)n0 * Hn;
    const __half* Bl = d_outW_l + (size_t)n0 * Hn;

    float accH[2][4][4] = {};
    float accL[2][4][4] = {};
    LOADC_O(0, 0, A, Bh, Bl);
    LOADC_O(1, 1, A, Bh, Bl);
#pragma unroll 1
    for (int c = 0; c < 8; ++c) {
      if (c < 7) cp_wait1(); else cp_wait0();
      __syncthreads();
      compute_chunk_o(accH, accL, su, c & 1, wm, wn, lane);
      __syncthreads();
      if (c + 2 < 8) LOADC_O(c + 2, c & 1, A, Bh, Bl);
    }

    int r0 = lane >> 2, c0 = (lane & 3) * 2;
#pragma unroll
    for (int nt = 0; nt < 4; ++nt) {
      int v = n0 + wn * 32 + nt * 8 + c0;
      if (v >= Vn) continue;
      float b0 = outb[v], b1 = outb[v + 1];
#pragma unroll
      for (int i = 0; i < 2; ++i) {
        int mrow = m0g + wm * 32 + i * 16 + r0;
#pragma unroll
        for (int h = 0; h < 2; ++h) {
          int m = mrow + h * 8;
          int bb = m & 255;
          float* dst = out + ((size_t)bb * Sn + t) * Vn + v;
          float2 o;
          o.x = accH[i][nt][h * 2 + 0] + accL[i][nt][h * 2 + 0] * (1.f / 4096.f) + b0;
          o.y = accH[i][nt][h * 2 + 1] + accL[i][nt][h * 2 + 1] * (1.f / 4096.f) + b1;
          *(float2*)dst = o;
        }
      }
    }
  }
}

extern "C" void kernel_launch(void* const* d_in, const int* in_sizes, int n_in,
                              void* d_out, int out_size) {
  const float* enc  = (const float*)d_in[0];
  const int*   tgt  = (const int*)  d_in[1];
  const float* emb  = (const float*)d_in[2];
  const float* Wih  = (const float*)d_in[3];
  const float* Whh  = (const float*)d_in[4];
  const float* bih  = (const float*)d_in[5];
  const float* bhh  = (const float*)d_in[6];
  // d_in[7..9] = attn_W, attn_b, v_w : dead (softmax over single source pos)
  const float* outW = (const float*)d_in[10];
  const float* outb = (const float*)d_in[11];
  float* out = (float*)d_out;

  cudaFuncSetAttribute(fused_kernel, cudaFuncAttributeMaxDynamicSharedMemorySize, FUSED_SMEM);

  prep_all<<<2177, 256>>>(enc, emb, Wih, Whh, bih, bhh, outW);
  fused_kernel<<<NCTA, 256, FUSED_SMEM>>>(tgt, outb, out);
}

// round 8
// speedup vs baseline: 3.8500x; 1.0977x over previous
#include <cuda_runtime.h>
#include <cuda_bf16.h>
#include <cuda_fp16.h>
#include <math.h>
#include <stdint.h>

#define Bn 256
#define Sn 141
#define Vn 1000
#define En 256
#define Hn 512
#define G4 2048   // 4*H
#define VP 1024   // padded vocab

#define NC_STEP 128         // recurrence CTAs (4 groups of 32)
#define NCTA    148         // persistent CTAs (1/SM)
#define NOUT    (Sn * 32)   // out tiles: per t, 2 m-tiles x 16 n-tiles

// ---------------- device scratch ----------------
__device__ float d_embgateP[(size_t)Vn * G4];     // [v][jp] fp32
__device__ float d_encgateP[(size_t)Bn * G4];     // [b][jp] fp32
__device__ __half d_Whh_h[(size_t)G4 * Hn];       // [jp][k] fp16 hi
__device__ __half d_Whh_l[(size_t)G4 * Hn];       // [jp][k] fp16 lo * 2^12
__device__ __half d_outW_h[(size_t)VP * Hn];      // [v][k] fp16 hi
__device__ __half d_outW_l[(size_t)VP * Hn];      // [v][k] fp16 lo * 2^12
__device__ __half d_hs_f16[(size_t)Sn * Bn * Hn]; // [t][b][k] fp16

// sync state (reset by prep kernel each replay); 128B-spaced counters
__device__ unsigned d_countg[4 * 32];
__device__ unsigned d_senseg[4 * 32];
__device__ unsigned d_wq;

__device__ __forceinline__ int jperm(int j) {
  return ((j & 511) >> 4) * 64 + (j >> 9) * 16 + (j & 15);
}

// ---------------- PTX helpers (plain sm_80+ only) ----------------
__device__ __forceinline__ void cp16(uint32_t dst, const void* src) {
  asm volatile("cp.async.cg.shared.global [%0], [%1], 16;" :: "r"(dst), "l"(src));
}
__device__ __forceinline__ void cp_commit() { asm volatile("cp.async.commit_group;"); }
__device__ __forceinline__ void cp_wait0() { asm volatile("cp.async.wait_group 0;" ::: "memory"); }
__device__ __forceinline__ void cp_wait1() { asm volatile("cp.async.wait_group 1;" ::: "memory"); }
__device__ __forceinline__ void cp_wait2() { asm volatile("cp.async.wait_group 2;" ::: "memory"); }

__device__ __forceinline__ void ldm4(uint32_t& r0, uint32_t& r1, uint32_t& r2, uint32_t& r3,
                                     uint32_t addr) {
  asm volatile("ldmatrix.sync.aligned.m8n8.x4.shared.b16 {%0,%1,%2,%3}, [%4];"
               : "=r"(r0), "=r"(r1), "=r"(r2), "=r"(r3) : "r"(addr));
}
__device__ __forceinline__ void mma_f16(float* d, const uint32_t* a, uint32_t b0, uint32_t b1) {
  asm volatile(
    "mma.sync.aligned.m16n8k16.row.col.f32.f16.f16.f32 "
    "{%0,%1,%2,%3}, {%4,%5,%6,%7}, {%8,%9}, {%0,%1,%2,%3};"
    : "+f"(d[0]), "+f"(d[1]), "+f"(d[2]), "+f"(d[3])
    : "r"(a[0]), "r"(a[1]), "r"(a[2]), "r"(a[3]), "r"(b0), "r"(b1));
}
__device__ __forceinline__ unsigned ld_acq(unsigned* p) {
  unsigned v;
  asm volatile("ld.acquire.gpu.u32 %0, [%1];" : "=r"(v) : "l"(p) : "memory");
  return v;
}

// ---------------- smem layout (recurrence) ----------------
// Resident B: 8 chunks x (64 rows x 128B), hi then lo.
#define BH_RES   0                     // 65536
#define BL_RES   65536                 // 65536
#define A_BUFS   131072                // 4 x 8192 = 32768
#define ADD_EMB  163840                // [64][64] f32 = 16384
#define ADD_ENC  180224                // 16384
#define GS_OFF   196608                // [64][68] f32 = 17408
#define GS_STRIDE 68
#define FUSED_SMEM 214016
// Out path (reuses offset 0): A fp16 128 rows + B hi/lo 64 rows per buffer
#define STG_O    32768
#define OA_OFF   0
#define OB_HI    16384
#define OB_LO    24576

// ---------------------------------------------------------------------------
// Merged prep kernel (same as R7)
// ---------------------------------------------------------------------------
#define MMA16(As, Bs) do {                                                       \
    _Pragma("unroll")                                                            \
    for (int kk = 0; kk < 16; ++kk) {                                            \
      float4 a = *(const float4*)&As[kk][ty * 4];                                \
      float4 b = *(const float4*)&Bs[kk][tx * 4];                                \
      acc[0][0] += a.x*b.x; acc[0][1] += a.x*b.y; acc[0][2] += a.x*b.z; acc[0][3] += a.x*b.w; \
      acc[1][0] += a.y*b.x; acc[1][1] += a.y*b.y; acc[1][2] += a.y*b.z; acc[1][3] += a.y*b.w; \
      acc[2][0] += a.z*b.x; acc[2][1] += a.z*b.y; acc[2][2] += a.z*b.z; acc[2][3] += a.z*b.w; \
      acc[3][0] += a.w*b.x; acc[3][1] += a.w*b.y; acc[3][2] += a.w*b.z; acc[3][3] += a.w*b.w; \
    } } while (0)

__global__ __launch_bounds__(256) void prep_all(
    const float* __restrict__ enc, const float* __restrict__ emb,
    const float* __restrict__ Wih, const float* __restrict__ Whh,
    const float* __restrict__ bih, const float* __restrict__ bhh,
    const float* __restrict__ outW) {
  __shared__ float As[16][64];
  __shared__ float Bs[16][64];
  int bid = blockIdx.x;
  int tid = threadIdx.x;

  if (bid < 640) {
    bool is_emb = bid < 512;
    int m0, n0;
    if (is_emb) { m0 = (bid & 15) * 64; n0 = (bid >> 4) * 64; }
    else        { int b2 = bid - 512; m0 = (b2 & 3) * 64; n0 = (b2 >> 2) * 64; }
    int tx = tid & 15, ty = tid >> 4;
    int lr = tid >> 2, lq = tid & 3;
    float acc[4][4] = {};
    for (int kc = 0; kc < En; kc += 16) {
      float4 av = make_float4(0.f, 0.f, 0.f, 0.f);
      float4 bv;
      if (is_emb) {
        if (m0 + lr < Vn)
          av = *(const float4*)(emb + (size_t)(m0 + lr) * En + kc + lq * 4);
        bv = *(const float4*)(Wih + (size_t)(n0 + lr) * (2 * En) + kc + lq * 4);
      } else {
        av = *(const float4*)(enc + (size_t)(m0 + lr) * En + kc + lq * 4);
        bv = *(const float4*)(Wih + (size_t)(n0 + lr) * (2 * En) + En + kc + lq * 4);
      }
      __syncthreads();
      As[lq*4+0][lr] = av.x; As[lq*4+1][lr] = av.y; As[lq*4+2][lr] = av.z; As[lq*4+3][lr] = av.w;
      Bs[lq*4+0][lr] = bv.x; Bs[lq*4+1][lr] = bv.y; Bs[lq*4+2][lr] = bv.z; Bs[lq*4+3][lr] = bv.w;
      __syncthreads();
      MMA16(As, Bs);
    }
#pragma unroll
    for (int ii = 0; ii < 4; ++ii) {
      int m = m0 + ty * 4 + ii;
      if (is_emb && m >= Vn) continue;
#pragma unroll
      for (int jj = 0; jj < 4; ++jj) {
        int n = n0 + tx * 4 + jj;
        if (is_emb)
          d_embgateP[(size_t)m * G4 + jperm(n)] = acc[ii][jj];
        else
          d_encgateP[(size_t)m * G4 + jperm(n)] = acc[ii][jj] + bih[n] + bhh[n];
      }
    }
  } else if (bid < 1664) {
    int i = (bid - 640) * 256 + tid;
    int e0 = i * 4;
    int j = e0 >> 9, k0 = e0 & 511;
    int jp = jperm(j);
    float4 x = *(const float4*)(Whh + e0);
    __half h[4], l[4];
    float xs[4] = {x.x, x.y, x.z, x.w};
#pragma unroll
    for (int q = 0; q < 4; ++q) {
      h[q] = __float2half_rn(xs[q]);
      l[q] = __float2half_rn((xs[q] - __half2float(h[q])) * 4096.f);
    }
    *(uint2*)(d_Whh_h + (size_t)jp * Hn + k0) = *(const uint2*)h;
    *(uint2*)(d_Whh_l + (size_t)jp * Hn + k0) = *(const uint2*)l;
  } else if (bid < 2176) {
    int i = (bid - 1664) * 256 + tid;
    int e0 = i * 4;
    int v = e0 >> 9;
    __half h[4], l[4];
    if (v < Vn) {
      float4 x = *(const float4*)(outW + e0 - (e0 >> 9) * Hn + (size_t)v * Hn);
      // note: e0 = v*512 + k0 and outW rows are 512 floats, so outW + e0 is exact
      x = *(const float4*)(outW + e0);
      float xs[4] = {x.x, x.y, x.z, x.w};
#pragma unroll
      for (int q = 0; q < 4; ++q) {
        h[q] = __float2half_rn(xs[q]);
        l[q] = __float2half_rn((xs[q] - __half2float(h[q])) * 4096.f);
      }
    } else {
#pragma unroll
      for (int q = 0; q < 4; ++q) { h[q] = __float2half_rn(0.f); l[q] = h[q]; }
    }
    *(uint2*)(d_outW_h + e0) = *(const uint2*)h;
    *(uint2*)(d_outW_l + e0) = *(const uint2*)l;
  } else {
    if (tid < 128) d_countg[tid] = 0;
    else if (tid < 256) d_senseg[tid - 128] = 0;
    if (tid == 0) d_wq = 0;
  }
}

// ============================================================================
// Recurrence: CTA tile 64x64, warp tile 16x32 (8 warps). B resident in smem.
// ============================================================================
#define LOADA_R(c, buf, AP)  do {                                                \
    int kc = (c) * 64;                                                           \
    uint32_t st = su + A_BUFS + (buf) * 8192;                                    \
    int row = tid >> 2;                                                          \
    int sg0 = (tid & 3) * 2;                                                     \
    uint32_t sw = (uint32_t)(row & 7) * 16;                                      \
    _Pragma("unroll")                                                            \
    for (int q = 0; q < 2; ++q) {                                                \
      int sg = sg0 + q;                                                          \
      uint32_t so = (uint32_t)row * 128 + (((uint32_t)(sg * 16)) ^ sw);          \
      cp16(st + so, (AP) + (size_t)row * Hn + kc + sg * 8);                      \
    }                                                                            \
    cp_commit();                                                                 \
  } while (0)

__device__ __forceinline__ void compute_chunk_r(
    float accH[4][4], float accL[4][4], uint32_t abase,
    uint32_t bhbase, uint32_t blbase, int wm, int wn, int lane) {
  int lr = lane & 7;
  int sel = lane >> 3;
  int a_roff = (sel & 1) * 8;
  int a_koff = (sel & 2) * 8;
  int b_koff = (sel & 1) * 16;
  int b_roff = (sel & 2) * 4;
  uint32_t swm = (uint32_t)(lr * 16);

#pragma unroll
  for (int ks = 0; ks < 4; ++ks) {
    int kb = ks * 32;
    uint32_t a[4], bh[2][4], bl[2][4];
    {
      int row = wm * 16 + lr + a_roff;
      uint32_t off = (uint32_t)row * 128 + (((uint32_t)(kb + a_koff)) ^ swm);
      ldm4(a[0], a[1], a[2], a[3], abase + off);
    }
#pragma unroll
    for (int p = 0; p < 2; ++p) {
      int row = wn * 32 + p * 16 + lr + b_roff;
      uint32_t off = (uint32_t)row * 128 + (((uint32_t)(kb + b_koff)) ^ swm);
      ldm4(bh[p][0], bh[p][1], bh[p][2], bh[p][3], bhbase + off);
      ldm4(bl[p][0], bl[p][1], bl[p][2], bl[p][3], blbase + off);
    }
#pragma unroll
    for (int nt = 0; nt < 4; ++nt) {
      int p = nt >> 1, q = (nt & 1) * 2;
      mma_f16(accH[nt], a, bh[p][q], bh[p][q + 1]);
      mma_f16(accL[nt], a, bl[p][q], bl[p][q + 1]);
    }
  }
}

// ============================================================================
// Out tile machinery: CTA tile 128x64, warp tile 32x32, 2-deep buffers.
// ============================================================================
#define LOADC_O(c, buf, AP, BhP, BlP)  do {                                      \
    int kc = (c) * 64;                                                           \
    uint32_t st = su + (buf) * STG_O;                                            \
    {                                                                            \
      int rowA = tid >> 1;                                                       \
      int sg0 = (tid & 1) * 4;                                                   \
      uint32_t swA = (uint32_t)(rowA & 7) * 16;                                  \
      _Pragma("unroll")                                                          \
      for (int q = 0; q < 4; ++q) {                                              \
        int sg = sg0 + q;                                                        \
        uint32_t so = (uint32_t)rowA * 128 + (((uint32_t)(sg * 16)) ^ swA);      \
        cp16(st + OA_OFF + so, (AP) + (size_t)rowA * Hn + kc + sg * 8);          \
      }                                                                          \
    }                                                                            \
    {                                                                            \
      int rB = tid >> 2;                                                         \
      int sg0 = (tid & 3) * 2;                                                   \
      uint32_t swB = (uint32_t)(rB & 7) * 16;                                    \
      _Pragma("unroll")                                                          \
      for (int q = 0; q < 2; ++q) {                                              \
        int sg = sg0 + q;                                                        \
        uint32_t so = (uint32_t)rB * 128 + (((uint32_t)(sg * 16)) ^ swB);        \
        cp16(st + OB_HI + so, (BhP) + (size_t)rB * Hn + kc + sg * 8);            \
        cp16(st + OB_LO + so, (BlP) + (size_t)rB * Hn + kc + sg * 8);            \
      }                                                                          \
    }                                                                            \
    cp_commit();                                                                 \
  } while (0)

__device__ __forceinline__ void compute_chunk_o(
    float accH[2][4][4], float accL[2][4][4], uint32_t su, int buf,
    int wm, int wn, int lane) {
  uint32_t base = su + buf * STG_O;
  int lr = lane & 7;
  int sel = lane >> 3;
  int a_roff = (sel & 1) * 8;
  int a_koff = (sel & 2) * 8;
  int b_koff = (sel & 1) * 16;
  int b_roff = (sel & 2) * 4;
  uint32_t swm = (uint32_t)(lr * 16);

#pragma unroll
  for (int ks = 0; ks < 4; ++ks) {
    int kb = ks * 32;
    uint32_t a[2][4], bh[2][4], bl[2][4];
#pragma unroll
    for (int i = 0; i < 2; ++i) {
      int row = wm * 32 + i * 16 + lr + a_roff;
      uint32_t off = (uint32_t)row * 128 + (((uint32_t)(kb + a_koff)) ^ swm);
      ldm4(a[i][0], a[i][1], a[i][2], a[i][3], base + OA_OFF + off);
    }
#pragma unroll
    for (int p = 0; p < 2; ++p) {
      int row = wn * 32 + p * 16 + lr + b_roff;
      uint32_t off = (uint32_t)row * 128 + (((uint32_t)(kb + b_koff)) ^ swm);
      ldm4(bh[p][0], bh[p][1], bh[p][2], bh[p][3], base + OB_HI + off);
      ldm4(bl[p][0], bl[p][1], bl[p][2], bl[p][3], base + OB_LO + off);
    }
#pragma unroll
    for (int i = 0; i < 2; ++i) {
#pragma unroll
      for (int nt = 0; nt < 4; ++nt) {
        int p = nt >> 1, q = (nt & 1) * 2;
        mma_f16(accH[i][nt], a[i], bh[p][q], bh[p][q + 1]);
        mma_f16(accL[i][nt], a[i], bl[p][q], bl[p][q + 1]);
      }
    }
  }
}

// ---------------------------------------------------------------------------
// Persistent fused kernel.
// ---------------------------------------------------------------------------
__global__ __launch_bounds__(256, 1) void fused_kernel(
    const int* __restrict__ tgt, const float* __restrict__ outb,
    float* __restrict__ out) {
  extern __shared__ __align__(1024) char smem[];
  __shared__ unsigned sidx;
  uint32_t su = (uint32_t)__cvta_generic_to_shared(smem);
  int tid = threadIdx.x;
  int lane = tid & 31, wid = tid >> 5;
  int wm = wid >> 1, wn = wid & 1;

  if (blockIdx.x < NC_STEP) {
    // ========== recurrence: CTA tile 64 b-rows x 64 jp-cols ==========
    int mi = blockIdx.x >> 5, nblk = blockIdx.x & 31;
    int m0 = mi * 64, n0 = nblk * 64;
    unsigned* myCount = &d_countg[mi * 32];
    unsigned* mySense = &d_senseg[mi * 32];

    // ---- resident loads: B (Whh tile, 8 chunks hi+lo) + enc addend ----
    {
      const __half* Bh = d_Whh_h + (size_t)n0 * Hn;
      const __half* Bl = d_Whh_l + (size_t)n0 * Hn;
      int row = tid >> 2;
      int sg0 = (tid & 3) * 2;
      uint32_t sw = (uint32_t)(row & 7) * 16;
#pragma unroll
      for (int c = 0; c < 8; ++c) {
#pragma unroll
        for (int q = 0; q < 2; ++q) {
          int sg = sg0 + q;
          uint32_t so = (uint32_t)row * 128 + (((uint32_t)(sg * 16)) ^ sw);
          cp16(su + BH_RES + c * 8192 + so, Bh + (size_t)row * Hn + c * 64 + sg * 8);
          cp16(su + BL_RES + c * 8192 + so, Bl + (size_t)row * Hn + c * 64 + sg * 8);
        }
      }
      int r = tid >> 2, sg0e = (tid & 3) * 4;
      const float* sc = d_encgateP + (size_t)(m0 + r) * G4 + n0;
      uint32_t dc = su + ADD_ENC + r * 256;
#pragma unroll
      for (int q = 0; q < 4; ++q)
        cp16(dc + (sg0e + q) * 16, sc + (sg0e + q) * 4);
      cp_commit();
      cp_wait0();
    }
    __syncthreads();

    int em_r = tid >> 2, em_sg = (tid & 3) * 4;
    int ep_m = tid >> 2, ep_k0 = (tid & 3) * 4;
    int ep_b = m0 + ep_m;
    int ep_kbase = nblk * 16 + ep_k0;
    const float* aE = (const float*)(smem + ADD_EMB) + ep_m * 64;
    const float* aC = (const float*)(smem + ADD_ENC) + ep_m * 64;
    float cpv[4] = {0.f, 0.f, 0.f, 0.f};

    for (int t = 0; t < Sn; ++t) {
      // emb addend for this step (group 0)
      {
        int tok = tgt[(size_t)(m0 + em_r) * Sn + t];
        const float* se = d_embgateP + (size_t)tok * G4 + n0;
        uint32_t de = su + ADD_EMB + em_r * 256;
#pragma unroll
        for (int q = 0; q < 4; ++q)
          cp16(de + (em_sg + q) * 16, se + (em_sg + q) * 4);
        cp_commit();
      }

      if (t > 0) {
        float accH[4][4] = {};
        float accL[4][4] = {};
        const __half* A = d_hs_f16 + ((size_t)(t - 1) * Bn + m0) * Hn;
        LOADA_R(0, 0, A);
        LOADA_R(1, 1, A);
        LOADA_R(2, 2, A);
#pragma unroll 1
        for (int c = 0; c < 8; ++c) {
          if (c <= 5) cp_wait2();
          else if (c == 6) cp_wait1();
          else cp_wait0();
          __syncthreads();
          compute_chunk_r(accH, accL,
                          su + A_BUFS + (c & 3) * 8192,
                          su + BH_RES + c * 8192,
                          su + BL_RES + c * 8192, wm, wn, lane);
          if (c + 3 < 8) LOADA_R(c + 3, (c + 3) & 3, A);
        }
        __syncthreads();
        // stage combined gates to Gs
        float* Gs = (float*)(smem + GS_OFF);
        int r0 = (lane >> 2), c0 = (lane & 3) * 2;
        const float kinv = 1.f / 4096.f;
#pragma unroll
        for (int nt = 0; nt < 4; ++nt) {
          int row = wm * 16 + r0;
          int col = wn * 32 + nt * 8 + c0;
          Gs[row * GS_STRIDE + col]           = accH[nt][0] + accL[nt][0] * kinv;
          Gs[row * GS_STRIDE + col + 1]       = accH[nt][1] + accL[nt][1] * kinv;
          Gs[(row + 8) * GS_STRIDE + col]     = accH[nt][2] + accL[nt][2] * kinv;
          Gs[(row + 8) * GS_STRIDE + col + 1] = accH[nt][3] + accL[nt][3] * kinv;
        }
      } else {
        cp_wait0();
      }
      __syncthreads();

      // ---- fused LSTM elementwise: 4 cells/thread ----
      const float* Gs = (const float*)(smem + GS_OFF);
      __half hf[4];
#pragma unroll
      for (int q = 0; q < 4; ++q) {
        int kk = ep_k0 + q;
        float gi = aE[kk]      + aC[kk];
        float gf = aE[16 + kk] + aC[16 + kk];
        float gg = aE[32 + kk] + aC[32 + kk];
        float go = aE[48 + kk] + aC[48 + kk];
        if (t > 0) {
          gi += Gs[ep_m * GS_STRIDE + kk];
          gf += Gs[ep_m * GS_STRIDE + 16 + kk];
          gg += Gs[ep_m * GS_STRIDE + 32 + kk];
          go += Gs[ep_m * GS_STRIDE + 48 + kk];
        }
        float iv = 1.f / (1.f + expf(-gi));
        float fv = 1.f / (1.f + expf(-gf));
        float gv = tanhf(gg);
        float ov = 1.f / (1.f + expf(-go));
        float cc = fv * cpv[q] + iv * gv;
        cpv[q] = cc;
        hf[q] = __float2half_rn(ov * tanhf(cc));
      }
      *(uint2*)(d_hs_f16 + ((size_t)t * Bn + ep_b) * Hn + ep_kbase) = *(const uint2*)hf;

      // ---- per-group (32-CTA) barrier ----
      __threadfence();
      __syncthreads();
      if (tid == 0) {
        unsigned old = atomicAdd(myCount, 1);
        if (old == 31) {
          atomicExch(myCount, 0);
          __threadfence();
          atomicAdd(mySense, 1);
        } else {
          while (ld_acq(mySense) < (unsigned)(t + 1)) { }
        }
      }
      __syncthreads();
    }
  }

  // ========== out-GEMM worker pool (all CTAs) ==========
  for (;;) {
    __syncthreads();
    if (tid == 0) sidx = atomicAdd(&d_wq, 1);
    __syncthreads();
    unsigned idx = sidx;
    if (idx >= NOUT) break;
    int t = idx >> 5;
    int sub = idx & 31;
    int mtile = sub >> 4;
    int m0g = t * Bn + mtile * 128;
    int n0 = (sub & 15) * 64;

    if (tid == 0) {
      unsigned* sA = &d_senseg[(mtile * 2) * 32];
      unsigned* sB = &d_senseg[(mtile * 2 + 1) * 32];
      while (ld_acq(sA) < (unsigned)(t + 1) || ld_acq(sB) < (unsigned)(t + 1))
        __nanosleep(128);
    }
    __syncthreads();

    const __half* A  = d_hs_f16 + (size_t)m0g * Hn;
    const __half* Bh = d_outW_h + (size_t)n0 * Hn;
    const __half* Bl = d_outW_l + (size_t)n0 * Hn;

    float accH[2][4][4] = {};
    float accL[2][4][4] = {};
    LOADC_O(0, 0, A, Bh, Bl);
    LOADC_O(1, 1, A, Bh, Bl);
#pragma unroll 1
    for (int c = 0; c < 8; ++c) {
      if (c < 7) cp_wait1(); else cp_wait0();
      __syncthreads();
      compute_chunk_o(accH, accL, su, c & 1, wm, wn, lane);
      __syncthreads();
      if (c + 2 < 8) LOADC_O(c + 2, c & 1, A, Bh, Bl);
    }

    int r0 = lane >> 2, c0 = (lane & 3) * 2;
#pragma unroll
    for (int nt = 0; nt < 4; ++nt) {
      int v = n0 + wn * 32 + nt * 8 + c0;
      if (v >= Vn) continue;
      float b0 = outb[v], b1 = outb[v + 1];
#pragma unroll
      for (int i = 0; i < 2; ++i) {
        int mrow = m0g + wm * 32 + i * 16 + r0;
#pragma unroll
        for (int h = 0; h < 2; ++h) {
          int m = mrow + h * 8;
          int bb = m & 255;
          float* dst = out + ((size_t)bb * Sn + t) * Vn + v;
          float2 o;
          o.x = accH[i][nt][h * 2 + 0] + accL[i][nt][h * 2 + 0] * (1.f / 4096.f) + b0;
          o.y = accH[i][nt][h * 2 + 1] + accL[i][nt][h * 2 + 1] * (1.f / 4096.f) + b1;
          *(float2*)dst = o;
        }
      }
    }
  }
}

extern "C" void kernel_launch(void* const* d_in, const int* in_sizes, int n_in,
                              void* d_out, int out_size) {
  const float* enc  = (const float*)d_in[0];
  const int*   tgt  = (const int*)  d_in[1];
  const float* emb  = (const float*)d_in[2];
  const float* Wih  = (const float*)d_in[3];
  const float* Whh  = (const float*)d_in[4];
  const float* bih  = (const float*)d_in[5];
  const float* bhh  = (const float*)d_in[6];
  // d_in[7..9] = attn_W, attn_b, v_w : dead (softmax over single source pos)
  const float* outW = (const float*)d_in[10];
  const float* outb = (const float*)d_in[11];
  float* out = (float*)d_out;

  cudaFuncSetAttribute(fused_kernel, cudaFuncAttributeMaxDynamicSharedMemorySize, FUSED_SMEM);

  prep_all<<<2177, 256>>>(enc, emb, Wih, Whh, bih, bhh, outW);
  fused_kernel<<<NCTA, 256, FUSED_SMEM>>>(tgt, outb, out);
}